// round 8
// baseline (speedup 1.0000x reference)
#include <cuda_runtime.h>
#include <cuda_bf16.h>
#include <float.h>
#include <stdint.h>

#define N_NODES 100000
#define N_EDGES 1600000
#define D 128
#define KDIM 256

// ---------------------------------------------------------------------------
// Device scratch (static per harness rules)
// ---------------------------------------------------------------------------
__device__ int   g_deg[N_NODES];
__device__ int   g_off[N_NODES];      // partial (pre-bsum) exclusive offsets
__device__ int   g_rank[N_EDGES];
__device__ int   g_adj[N_EDGES];
__device__ int   g_bsum[128];
__device__ int   g_bsumoff[128];
__device__ __align__(16) __nv_bfloat16 g_Wh[128 * KDIM];  // W split hi
__device__ __align__(16) __nv_bfloat16 g_Wl[128 * KDIM];  // W split lo

// ===========================================================================
// CSR build
// ===========================================================================
__global__ void __launch_bounds__(256) zero_deg_kernel() {
    int i = blockIdx.x * blockDim.x + threadIdx.x;
    if (i < N_NODES) g_deg[i] = 0;
}

// histogram + per-edge rank; 8 edges/thread for ILP (atomic-latency bound)
__global__ void __launch_bounds__(256) hist_kernel(const int* __restrict__ src) {
    int i = blockIdx.x * blockDim.x + threadIdx.x;   // over E/8
    if (i < N_EDGES / 8) {
        int4 s0 = reinterpret_cast<const int4*>(src)[i * 2 + 0];
        int4 s1 = reinterpret_cast<const int4*>(src)[i * 2 + 1];
        int4 r0, r1;
        r0.x = atomicAdd(&g_deg[s0.x], 1);
        r0.y = atomicAdd(&g_deg[s0.y], 1);
        r0.z = atomicAdd(&g_deg[s0.z], 1);
        r0.w = atomicAdd(&g_deg[s0.w], 1);
        r1.x = atomicAdd(&g_deg[s1.x], 1);
        r1.y = atomicAdd(&g_deg[s1.y], 1);
        r1.z = atomicAdd(&g_deg[s1.z], 1);
        r1.w = atomicAdd(&g_deg[s1.w], 1);
        reinterpret_cast<int4*>(g_rank)[i * 2 + 0] = r0;
        reinterpret_cast<int4*>(g_rank)[i * 2 + 1] = r1;
    }
}

__global__ void __launch_bounds__(1024) scan_partial_kernel() {
    __shared__ int s[1024];
    int i = blockIdx.x * 1024 + threadIdx.x;
    int v = (i < N_NODES) ? g_deg[i] : 0;
    s[threadIdx.x] = v;
    __syncthreads();
#pragma unroll
    for (int ofs = 1; ofs < 1024; ofs <<= 1) {
        int t = (threadIdx.x >= ofs) ? s[threadIdx.x - ofs] : 0;
        __syncthreads();
        s[threadIdx.x] += t;
        __syncthreads();
    }
    if (i < N_NODES) g_off[i] = s[threadIdx.x] - v;
    if (threadIdx.x == 1023) g_bsum[blockIdx.x] = s[1023];
}

__global__ void __launch_bounds__(128) scan_bsums_kernel(int nblocks) {
    __shared__ int s[128];
    int v = (threadIdx.x < nblocks) ? g_bsum[threadIdx.x] : 0;
    s[threadIdx.x] = v;
    __syncthreads();
#pragma unroll
    for (int ofs = 1; ofs < 128; ofs <<= 1) {
        int t = (threadIdx.x >= ofs) ? s[threadIdx.x - ofs] : 0;
        __syncthreads();
        s[threadIdx.x] += t;
        __syncthreads();
    }
    g_bsumoff[threadIdx.x] = s[threadIdx.x] - v;
}

// atomic-free scatter (rank precomputed); offsets patched with bsumoff here
__global__ void __launch_bounds__(256) fill_adj_kernel(const int* __restrict__ src,
                                                       const int* __restrict__ dst) {
    int i = blockIdx.x * blockDim.x + threadIdx.x;   // over E/4
    if (i < N_EDGES / 4) {
        int4 s = reinterpret_cast<const int4*>(src)[i];
        int4 d = reinterpret_cast<const int4*>(dst)[i];
        int4 r = reinterpret_cast<const int4*>(g_rank)[i];
        g_adj[g_off[s.x] + g_bsumoff[s.x >> 10] + r.x] = d.x;
        g_adj[g_off[s.y] + g_bsumoff[s.y >> 10] + r.y] = d.y;
        g_adj[g_off[s.z] + g_bsumoff[s.z >> 10] + r.z] = d.z;
        g_adj[g_off[s.w] + g_bsumoff[s.w >> 10] + r.w] = d.w;
    }
}

// ===========================================================================
// W hi/lo bf16 split
// ===========================================================================
__global__ void __launch_bounds__(256) wsplit_kernel(const float* __restrict__ W) {
    int i = blockIdx.x * blockDim.x + threadIdx.x;
    if (i < 128 * KDIM) {
        float v = W[i];
        __nv_bfloat16 h = __float2bfloat16_rn(v);
        g_Wh[i] = h;
        g_Wl[i] = __float2bfloat16_rn(v - __bfloat162float(h));
    }
}

// ===========================================================================
// Fused aggregate + GEMM, wave-parity anti-phased + fine interleave:
//   P0: aggA | C0 C1 | aggB | C2 C3 | C4..7
//   P1: C0 C1 | aggA | C2 C3 | aggB | C4..7
// Co-resident CTAs are bid and bid+148 (one wave apart) -> (bid/148)&1 gives
// them OPPOSITE parity, so one CTA is on the LTS while the other is on tensor.
// ===========================================================================
__device__ __forceinline__ uint32_t smem_u32(const void* p) {
    uint32_t a;
    asm("{ .reg .u64 t; cvta.to.shared.u64 t, %1; cvt.u32.u64 %0, t; }"
        : "=r"(a) : "l"(p));
    return a;
}

__device__ __forceinline__ uint32_t sw64(uint32_t b) { return b ^ ((b >> 3) & 0x30); }

__device__ __forceinline__ void ldsm_x4(uint32_t& r0, uint32_t& r1, uint32_t& r2,
                                        uint32_t& r3, uint32_t addr) {
    asm volatile("ldmatrix.sync.aligned.m8n8.x4.shared.b16 {%0,%1,%2,%3}, [%4];"
                 : "=r"(r0), "=r"(r1), "=r"(r2), "=r"(r3) : "r"(addr));
}

__device__ __forceinline__ void mma_bf16(float* c, uint32_t a0, uint32_t a1,
                                         uint32_t a2, uint32_t a3,
                                         uint32_t b0, uint32_t b1) {
    asm volatile(
        "mma.sync.aligned.m16n8k16.row.col.f32.bf16.bf16.f32 "
        "{%0,%1,%2,%3},{%4,%5,%6,%7},{%8,%9},{%0,%1,%2,%3};"
        : "+f"(c[0]), "+f"(c[1]), "+f"(c[2]), "+f"(c[3])
        : "r"(a0), "r"(a1), "r"(a2), "r"(a3), "r"(b0), "r"(b1));
}

__device__ __forceinline__ float4 max4(float4 a, float4 b) {
    return make_float4(fmaxf(a.x, b.x), fmaxf(a.y, b.y),
                       fmaxf(a.z, b.z), fmaxf(a.w, b.w));
}

__device__ __forceinline__ void split_pair(float2 v, uint32_t& hi, uint32_t& lo) {
    __nv_bfloat162 h = __float22bfloat162_rn(v);
    float2 r = make_float2(v.x - __low2float(h), v.y - __high2float(h));
    __nv_bfloat162 l = __float22bfloat162_rn(r);
    hi = *reinterpret_cast<uint32_t*>(&h);
    lo = *reinterpret_cast<uint32_t*>(&l);
}

// dynamic smem layout (96 KB total):
//   [0,      65536): aggC[4 chunks][hi 8KB | lo 8KB]
//   [65536,  73728): sAh   (H-chunk staging)
//   [73728,  81920): sAl
//   [81920,  90112): sBh
//   [90112,  98304): sBl
#define SM_AGG   0
#define SM_AH    65536
#define SM_AL    73728
#define SM_BH    81920
#define SM_BL    90112
#define SM_TOTAL 98304

struct GemmCtx {
    uint8_t* smem;
    const float* H;
    int mblk, tid, lane, warp_m, warp_n, lsub, lr;
    uint32_t bAh0, bAl0, bBh, bBl, bAgg;
};

// aggregate 8 rows per warp: rows [wid*16 + i0, wid*16 + i0 + 8)
__device__ __forceinline__ void do_aggregate(const GemmCtx& g, int i0) {
    const int lane = g.lane;
    const int wid  = g.tid >> 5;
    const int q  = lane & 7;
    const int ch = lane >> 3;
    uint8_t* aggHi = g.smem + SM_AGG + ch * 16384;
    uint8_t* aggLo = aggHi + 8192;
    const float* H = g.H;

    for (int i = i0; i < i0 + 8; i++) {
        int mloc  = wid * 16 + i;
        int gnode = g.mblk + mloc;
        float4 m = make_float4(-FLT_MAX, -FLT_MAX, -FLT_MAX, -FLT_MAX);
        int deg = 0;
        if (gnode < N_NODES) {
            int off = g_off[gnode] + g_bsumoff[gnode >> 10];
            deg = g_deg[gnode];
            int j = 0;
            for (; j + 8 <= deg; j += 8) {
                float4 v0 = *reinterpret_cast<const float4*>(H + (size_t)g_adj[off + j + 0] * D + lane * 4);
                float4 v1 = *reinterpret_cast<const float4*>(H + (size_t)g_adj[off + j + 1] * D + lane * 4);
                float4 v2 = *reinterpret_cast<const float4*>(H + (size_t)g_adj[off + j + 2] * D + lane * 4);
                float4 v3 = *reinterpret_cast<const float4*>(H + (size_t)g_adj[off + j + 3] * D + lane * 4);
                float4 v4 = *reinterpret_cast<const float4*>(H + (size_t)g_adj[off + j + 4] * D + lane * 4);
                float4 v5 = *reinterpret_cast<const float4*>(H + (size_t)g_adj[off + j + 5] * D + lane * 4);
                float4 v6 = *reinterpret_cast<const float4*>(H + (size_t)g_adj[off + j + 6] * D + lane * 4);
                float4 v7 = *reinterpret_cast<const float4*>(H + (size_t)g_adj[off + j + 7] * D + lane * 4);
                m = max4(m, max4(max4(max4(v0, v1), max4(v2, v3)),
                                 max4(max4(v4, v5), max4(v6, v7))));
            }
            for (; j < deg; j++) {
                m = max4(m, *reinterpret_cast<const float4*>(
                                 H + (size_t)g_adj[off + j] * D + lane * 4));
            }
        }
        if (deg == 0) m = make_float4(0.f, 0.f, 0.f, 0.f);

        uint32_t h01, l01, h23, l23;
        split_pair(make_float2(m.x, m.y), h01, l01);
        split_pair(make_float2(m.z, m.w), h23, l23);
        uint32_t sb = sw64((uint32_t)(mloc * 64 + q * 8));
        *reinterpret_cast<uint2*>(aggHi + sb) = make_uint2(h01, h23);
        *reinterpret_cast<uint2*>(aggLo + sb) = make_uint2(l01, l23);
    }
}

__device__ __forceinline__ void do_chunk(const GemmCtx& g, int c, float acc[2][8][4]) {
    const int kc = c * 32;
    uint8_t* smem = g.smem;
    const int tid = g.tid;

    // ---- stage A from H (chunks 0-3 only; 4-7 read agg smem) ----
    if (c < 4) {
#pragma unroll
        for (int i = 0; i < 4; i++) {
            int idx = i * 256 + tid;
            int m = idx >> 3, q = idx & 7;
            int gm = g.mblk + m;
            float4 v = make_float4(0.f, 0.f, 0.f, 0.f);
            if (gm < N_NODES)
                v = *reinterpret_cast<const float4*>(g.H + (size_t)gm * D + kc + q * 4);
            uint32_t h01, l01, h23, l23;
            split_pair(make_float2(v.x, v.y), h01, l01);
            split_pair(make_float2(v.z, v.w), h23, l23);
            uint32_t sb = sw64((uint32_t)(m * 64 + q * 8));
            *reinterpret_cast<uint2*>(smem + SM_AH + sb) = make_uint2(h01, h23);
            *reinterpret_cast<uint2*>(smem + SM_AL + sb) = make_uint2(l01, l23);
        }
    }

    // ---- stage B ----
#pragma unroll
    for (int i = 0; i < 2; i++) {
        int idx = i * 256 + tid;
        int n = idx >> 2, u = idx & 3;
        size_t srcoff = (size_t)n * KDIM + kc;   // bf16 elems
        uint32_t sb = sw64((uint32_t)(n * 64 + u * 16));
        *reinterpret_cast<uint4*>(smem + SM_BH + sb) =
            *reinterpret_cast<const uint4*>(
                reinterpret_cast<const uint8_t*>(g_Wh) + srcoff * 2 + u * 16);
        *reinterpret_cast<uint4*>(smem + SM_BL + sb) =
            *reinterpret_cast<const uint4*>(
                reinterpret_cast<const uint8_t*>(g_Wl) + srcoff * 2 + u * 16);
    }
    __syncthreads();

    const uint32_t aH = (c < 4) ? g.bAh0 : (g.bAgg + (uint32_t)(c - 4) * 16384u);
    const uint32_t aL = (c < 4) ? g.bAl0 : (aH + 8192u);

#pragma unroll
    for (int ks = 0; ks < 2; ks++) {
        const int k0 = ks * 16;
        uint32_t Ah[2][4], Al[2][4];
#pragma unroll
        for (int f = 0; f < 2; f++) {
            int row = g.warp_m * 32 + f * 16 + (g.lsub & 1) * 8 + g.lr;
            int kb  = k0 + (g.lsub >> 1) * 8;
            uint32_t ofs = sw64((uint32_t)(row * 64 + kb * 2));
            ldsm_x4(Ah[f][0], Ah[f][1], Ah[f][2], Ah[f][3], aH + ofs);
            ldsm_x4(Al[f][0], Al[f][1], Al[f][2], Al[f][3], aL + ofs);
        }
#pragma unroll
        for (int np = 0; np < 4; np++) {
            int n  = g.warp_n * 64 + np * 16 + (g.lsub >> 1) * 8 + g.lr;
            int kb = k0 + (g.lsub & 1) * 8;
            uint32_t ofs = sw64((uint32_t)(n * 64 + kb * 2));
            uint32_t Bh[4], Bl[4];
            ldsm_x4(Bh[0], Bh[1], Bh[2], Bh[3], g.bBh + ofs);
            ldsm_x4(Bl[0], Bl[1], Bl[2], Bl[3], g.bBl + ofs);
#pragma unroll
            for (int f = 0; f < 2; f++) {
                mma_bf16(acc[f][np * 2 + 0], Ah[f][0], Ah[f][1], Ah[f][2], Ah[f][3], Bh[0], Bh[1]);
                mma_bf16(acc[f][np * 2 + 1], Ah[f][0], Ah[f][1], Ah[f][2], Ah[f][3], Bh[2], Bh[3]);
                mma_bf16(acc[f][np * 2 + 0], Ah[f][0], Ah[f][1], Ah[f][2], Ah[f][3], Bl[0], Bl[1]);
                mma_bf16(acc[f][np * 2 + 1], Ah[f][0], Ah[f][1], Ah[f][2], Ah[f][3], Bl[2], Bl[3]);
                mma_bf16(acc[f][np * 2 + 0], Al[f][0], Al[f][1], Al[f][2], Al[f][3], Bh[0], Bh[1]);
                mma_bf16(acc[f][np * 2 + 1], Al[f][0], Al[f][1], Al[f][2], Al[f][3], Bh[2], Bh[3]);
            }
        }
    }
    __syncthreads();
}

__global__ void __launch_bounds__(256, 2) fused_kernel(
    const float* __restrict__ H,
    const float* __restrict__ bias,
    float* __restrict__ out)
{
    extern __shared__ __align__(16) uint8_t smem[];

    GemmCtx g;
    g.smem   = smem;
    g.H      = H;
    g.tid    = threadIdx.x;
    g.lane   = g.tid & 31;
    g.mblk   = blockIdx.x * 128;
    int wid  = g.tid >> 5;
    g.warp_m = wid >> 1;
    g.warp_n = wid & 1;
    g.lsub   = g.lane >> 3;
    g.lr     = g.lane & 7;
    g.bAh0   = smem_u32(smem + SM_AH);
    g.bAl0   = smem_u32(smem + SM_AL);
    g.bBh    = smem_u32(smem + SM_BH);
    g.bBl    = smem_u32(smem + SM_BL);
    g.bAgg   = smem_u32(smem + SM_AGG);

    float acc[2][8][4];
#pragma unroll
    for (int f = 0; f < 2; f++)
#pragma unroll
        for (int t = 0; t < 8; t++)
#pragma unroll
            for (int i = 0; i < 4; i++) acc[f][t][i] = 0.f;

    // co-resident CTAs are one wave apart -> opposite parity
    const bool aggFirst = (((blockIdx.x / 148) & 1) == 0);

    if (aggFirst) do_aggregate(g, 0);
    do_chunk(g, 0, acc);
    do_chunk(g, 1, acc);
    do_aggregate(g, aggFirst ? 8 : 0);
    do_chunk(g, 2, acc);
    do_chunk(g, 3, acc);
    if (!aggFirst) do_aggregate(g, 8);
    // chunk 4's staging __syncthreads orders agg smem writes before ldsm reads
    for (int c = 4; c < 8; c++) do_chunk(g, c, acc);

    // ---- epilogue: add bias, store ----
    const int mbase = g.mblk + g.warp_m * 32 + (g.lane >> 2);
#pragma unroll
    for (int f = 0; f < 2; f++) {
        int row0 = mbase + f * 16;
        int row1 = row0 + 8;
#pragma unroll
        for (int t = 0; t < 8; t++) {
            int col = g.warp_n * 64 + t * 8 + (g.lane & 3) * 2;
            float2 bv = *reinterpret_cast<const float2*>(bias + col);
            if (row0 < N_NODES) {
                float2 o = make_float2(acc[f][t][0] + bv.x, acc[f][t][1] + bv.y);
                *reinterpret_cast<float2*>(out + (size_t)row0 * D + col) = o;
            }
            if (row1 < N_NODES) {
                float2 o = make_float2(acc[f][t][2] + bv.x, acc[f][t][3] + bv.y);
                *reinterpret_cast<float2*>(out + (size_t)row1 * D + col) = o;
            }
        }
    }
}

// ===========================================================================
// Launch (single stream)
// ===========================================================================
extern "C" void kernel_launch(void* const* d_in, const int* in_sizes, int n_in,
                              void* d_out, int out_size) {
    const float* H   = (const float*)d_in[0];
    const int*   src = (const int*)d_in[1];
    const int*   dst = (const int*)d_in[2];
    const float* W   = (const float*)d_in[3];
    const float* b   = (const float*)d_in[4];
    float*       out = (float*)d_out;

    cudaFuncSetAttribute(fused_kernel,
                         cudaFuncAttributeMaxDynamicSharedMemorySize, SM_TOTAL);

    const int nb_nodes = (N_NODES + 255) / 256;
    const int nb_e4    = (N_EDGES / 4 + 255) / 256;
    const int nb_e8    = (N_EDGES / 8 + 255) / 256;
    const int nb_scan  = (N_NODES + 1023) / 1024;   // 98
    const int nb_gemm  = (N_NODES + 127) / 128;     // 782

    wsplit_kernel<<<(128 * KDIM + 255) / 256, 256>>>(W);
    zero_deg_kernel<<<nb_nodes, 256>>>();
    hist_kernel<<<nb_e8, 256>>>(src);
    scan_partial_kernel<<<nb_scan, 1024>>>();
    scan_bsums_kernel<<<1, 128>>>(nb_scan);
    fill_adj_kernel<<<nb_e4, 256>>>(src, dst);

    fused_kernel<<<nb_gemm, 256, SM_TOTAL>>>(H, b, out);
}

// round 9
// speedup vs baseline: 1.0253x; 1.0253x over previous
#include <cuda_runtime.h>
#include <cuda_bf16.h>
#include <float.h>
#include <stdint.h>

#define N_NODES 100000
#define N_EDGES 1600000
#define D 128
#define KDIM 256

// ---------------------------------------------------------------------------
// Device scratch (static per harness rules)
// ---------------------------------------------------------------------------
__device__ int   g_deg[N_NODES];
__device__ int   g_off[N_NODES];      // partial (pre-bsum) exclusive offsets
__device__ int   g_rank[N_EDGES];
__device__ int   g_adj[N_EDGES];
__device__ int   g_bsum[128];
__device__ int   g_bsumoff[128];
__device__ __align__(16) __nv_bfloat16 g_Wh[128 * KDIM];  // W split hi
__device__ __align__(16) __nv_bfloat16 g_Wl[128 * KDIM];  // W split lo

// ===========================================================================
// init: zero degree counters + split W to bf16 hi/lo (one kernel, one launch)
// ===========================================================================
__global__ void __launch_bounds__(256) init_kernel(const float* __restrict__ W) {
    int i = blockIdx.x * blockDim.x + threadIdx.x;
    if (i < N_NODES) g_deg[i] = 0;
    if (i < 128 * KDIM) {
        float v = W[i];
        __nv_bfloat16 h = __float2bfloat16_rn(v);
        g_Wh[i] = h;
        g_Wl[i] = __float2bfloat16_rn(v - __bfloat162float(h));
    }
}

// histogram + per-edge rank; 8 edges/thread for ILP (atomic-latency bound)
__global__ void __launch_bounds__(256) hist_kernel(const int* __restrict__ src) {
    int i = blockIdx.x * blockDim.x + threadIdx.x;   // over E/8
    if (i < N_EDGES / 8) {
        int4 s0 = reinterpret_cast<const int4*>(src)[i * 2 + 0];
        int4 s1 = reinterpret_cast<const int4*>(src)[i * 2 + 1];
        int4 r0, r1;
        r0.x = atomicAdd(&g_deg[s0.x], 1);
        r0.y = atomicAdd(&g_deg[s0.y], 1);
        r0.z = atomicAdd(&g_deg[s0.z], 1);
        r0.w = atomicAdd(&g_deg[s0.w], 1);
        r1.x = atomicAdd(&g_deg[s1.x], 1);
        r1.y = atomicAdd(&g_deg[s1.y], 1);
        r1.z = atomicAdd(&g_deg[s1.z], 1);
        r1.w = atomicAdd(&g_deg[s1.w], 1);
        reinterpret_cast<int4*>(g_rank)[i * 2 + 0] = r0;
        reinterpret_cast<int4*>(g_rank)[i * 2 + 1] = r1;
    }
}

__global__ void __launch_bounds__(1024) scan_partial_kernel() {
    __shared__ int s[1024];
    int i = blockIdx.x * 1024 + threadIdx.x;
    int v = (i < N_NODES) ? g_deg[i] : 0;
    s[threadIdx.x] = v;
    __syncthreads();
#pragma unroll
    for (int ofs = 1; ofs < 1024; ofs <<= 1) {
        int t = (threadIdx.x >= ofs) ? s[threadIdx.x - ofs] : 0;
        __syncthreads();
        s[threadIdx.x] += t;
        __syncthreads();
    }
    if (i < N_NODES) g_off[i] = s[threadIdx.x] - v;
    if (threadIdx.x == 1023) g_bsum[blockIdx.x] = s[1023];
}

__global__ void __launch_bounds__(128) scan_bsums_kernel(int nblocks) {
    __shared__ int s[128];
    int v = (threadIdx.x < nblocks) ? g_bsum[threadIdx.x] : 0;
    s[threadIdx.x] = v;
    __syncthreads();
#pragma unroll
    for (int ofs = 1; ofs < 128; ofs <<= 1) {
        int t = (threadIdx.x >= ofs) ? s[threadIdx.x - ofs] : 0;
        __syncthreads();
        s[threadIdx.x] += t;
        __syncthreads();
    }
    g_bsumoff[threadIdx.x] = s[threadIdx.x] - v;
}

// atomic-free scatter (rank precomputed); offsets patched with bsumoff here
__global__ void __launch_bounds__(256) fill_adj_kernel(const int* __restrict__ src,
                                                       const int* __restrict__ dst) {
    int i = blockIdx.x * blockDim.x + threadIdx.x;   // over E/8
    if (i < N_EDGES / 8) {
#pragma unroll
        for (int h = 0; h < 2; h++) {
            int4 s = reinterpret_cast<const int4*>(src)[i * 2 + h];
            int4 d = reinterpret_cast<const int4*>(dst)[i * 2 + h];
            int4 r = reinterpret_cast<const int4*>(g_rank)[i * 2 + h];
            g_adj[g_off[s.x] + g_bsumoff[s.x >> 10] + r.x] = d.x;
            g_adj[g_off[s.y] + g_bsumoff[s.y >> 10] + r.y] = d.y;
            g_adj[g_off[s.z] + g_bsumoff[s.z >> 10] + r.z] = d.z;
            g_adj[g_off[s.w] + g_bsumoff[s.w >> 10] + r.w] = d.w;
        }
    }
}

// ===========================================================================
// Fused GEMM + aggregate with PDL:
//   chunks 0-3 (H@W1, no CSR dep) -> cudaGridDependencySynchronize()
//   -> aggregate (reads g_adj) -> chunks 4-7 (agg@W2)
// ===========================================================================
__device__ __forceinline__ uint32_t smem_u32(const void* p) {
    uint32_t a;
    asm("{ .reg .u64 t; cvta.to.shared.u64 t, %1; cvt.u32.u64 %0, t; }"
        : "=r"(a) : "l"(p));
    return a;
}

__device__ __forceinline__ uint32_t sw64(uint32_t b) { return b ^ ((b >> 3) & 0x30); }

__device__ __forceinline__ void ldsm_x4(uint32_t& r0, uint32_t& r1, uint32_t& r2,
                                        uint32_t& r3, uint32_t addr) {
    asm volatile("ldmatrix.sync.aligned.m8n8.x4.shared.b16 {%0,%1,%2,%3}, [%4];"
                 : "=r"(r0), "=r"(r1), "=r"(r2), "=r"(r3) : "r"(addr));
}

__device__ __forceinline__ void mma_bf16(float* c, uint32_t a0, uint32_t a1,
                                         uint32_t a2, uint32_t a3,
                                         uint32_t b0, uint32_t b1) {
    asm volatile(
        "mma.sync.aligned.m16n8k16.row.col.f32.bf16.bf16.f32 "
        "{%0,%1,%2,%3},{%4,%5,%6,%7},{%8,%9},{%0,%1,%2,%3};"
        : "+f"(c[0]), "+f"(c[1]), "+f"(c[2]), "+f"(c[3])
        : "r"(a0), "r"(a1), "r"(a2), "r"(a3), "r"(b0), "r"(b1));
}

__device__ __forceinline__ float4 max4(float4 a, float4 b) {
    return make_float4(fmaxf(a.x, b.x), fmaxf(a.y, b.y),
                       fmaxf(a.z, b.z), fmaxf(a.w, b.w));
}

__device__ __forceinline__ void split_pair(float2 v, uint32_t& hi, uint32_t& lo) {
    __nv_bfloat162 h = __float22bfloat162_rn(v);
    float2 r = make_float2(v.x - __low2float(h), v.y - __high2float(h));
    __nv_bfloat162 l = __float22bfloat162_rn(r);
    hi = *reinterpret_cast<uint32_t*>(&h);
    lo = *reinterpret_cast<uint32_t*>(&l);
}

// dynamic smem layout (96 KB total):
//   [0,      65536): aggC[4 chunks][hi 8KB | lo 8KB]
//   [65536,  73728): sAh   (H-chunk staging)
//   [73728,  81920): sAl
//   [81920,  90112): sBh
//   [90112,  98304): sBl
#define SM_AGG   0
#define SM_AH    65536
#define SM_AL    73728
#define SM_BH    81920
#define SM_BL    90112
#define SM_TOTAL 98304

struct GemmCtx {
    uint8_t* smem;
    const float* H;
    int mblk, tid, lane, warp_m, warp_n, lsub, lr;
    uint32_t bAh0, bAl0, bBh, bBl, bAgg;
};

// aggregate all 16 rows per warp
__device__ __forceinline__ void do_aggregate(const GemmCtx& g) {
    const int lane = g.lane;
    const int wid  = g.tid >> 5;
    const int q  = lane & 7;
    const int ch = lane >> 3;
    uint8_t* aggHi = g.smem + SM_AGG + ch * 16384;
    uint8_t* aggLo = aggHi + 8192;
    const float* H = g.H;

    for (int i = 0; i < 16; i++) {
        int mloc  = wid * 16 + i;
        int gnode = g.mblk + mloc;
        float4 m = make_float4(-FLT_MAX, -FLT_MAX, -FLT_MAX, -FLT_MAX);
        int deg = 0;
        if (gnode < N_NODES) {
            int off = g_off[gnode] + g_bsumoff[gnode >> 10];
            deg = g_deg[gnode];
            int j = 0;
            for (; j + 8 <= deg; j += 8) {
                float4 v0 = *reinterpret_cast<const float4*>(H + (size_t)g_adj[off + j + 0] * D + lane * 4);
                float4 v1 = *reinterpret_cast<const float4*>(H + (size_t)g_adj[off + j + 1] * D + lane * 4);
                float4 v2 = *reinterpret_cast<const float4*>(H + (size_t)g_adj[off + j + 2] * D + lane * 4);
                float4 v3 = *reinterpret_cast<const float4*>(H + (size_t)g_adj[off + j + 3] * D + lane * 4);
                float4 v4 = *reinterpret_cast<const float4*>(H + (size_t)g_adj[off + j + 4] * D + lane * 4);
                float4 v5 = *reinterpret_cast<const float4*>(H + (size_t)g_adj[off + j + 5] * D + lane * 4);
                float4 v6 = *reinterpret_cast<const float4*>(H + (size_t)g_adj[off + j + 6] * D + lane * 4);
                float4 v7 = *reinterpret_cast<const float4*>(H + (size_t)g_adj[off + j + 7] * D + lane * 4);
                m = max4(m, max4(max4(max4(v0, v1), max4(v2, v3)),
                                 max4(max4(v4, v5), max4(v6, v7))));
            }
            for (; j < deg; j++) {
                m = max4(m, *reinterpret_cast<const float4*>(
                                 H + (size_t)g_adj[off + j] * D + lane * 4));
            }
        }
        if (deg == 0) m = make_float4(0.f, 0.f, 0.f, 0.f);

        uint32_t h01, l01, h23, l23;
        split_pair(make_float2(m.x, m.y), h01, l01);
        split_pair(make_float2(m.z, m.w), h23, l23);
        uint32_t sb = sw64((uint32_t)(mloc * 64 + q * 8));
        *reinterpret_cast<uint2*>(aggHi + sb) = make_uint2(h01, h23);
        *reinterpret_cast<uint2*>(aggLo + sb) = make_uint2(l01, l23);
    }
}

__device__ __forceinline__ void do_chunk(const GemmCtx& g, int c, float acc[2][8][4]) {
    const int kc = c * 32;
    uint8_t* smem = g.smem;
    const int tid = g.tid;

    // ---- stage A from H (chunks 0-3 only; 4-7 read agg smem) ----
    if (c < 4) {
#pragma unroll
        for (int i = 0; i < 4; i++) {
            int idx = i * 256 + tid;
            int m = idx >> 3, q = idx & 7;
            int gm = g.mblk + m;
            float4 v = make_float4(0.f, 0.f, 0.f, 0.f);
            if (gm < N_NODES)
                v = *reinterpret_cast<const float4*>(g.H + (size_t)gm * D + kc + q * 4);
            uint32_t h01, l01, h23, l23;
            split_pair(make_float2(v.x, v.y), h01, l01);
            split_pair(make_float2(v.z, v.w), h23, l23);
            uint32_t sb = sw64((uint32_t)(m * 64 + q * 8));
            *reinterpret_cast<uint2*>(smem + SM_AH + sb) = make_uint2(h01, h23);
            *reinterpret_cast<uint2*>(smem + SM_AL + sb) = make_uint2(l01, l23);
        }
    }

    // ---- stage B ----
#pragma unroll
    for (int i = 0; i < 2; i++) {
        int idx = i * 256 + tid;
        int n = idx >> 2, u = idx & 3;
        size_t srcoff = (size_t)n * KDIM + kc;   // bf16 elems
        uint32_t sb = sw64((uint32_t)(n * 64 + u * 16));
        *reinterpret_cast<uint4*>(smem + SM_BH + sb) =
            *reinterpret_cast<const uint4*>(
                reinterpret_cast<const uint8_t*>(g_Wh) + srcoff * 2 + u * 16);
        *reinterpret_cast<uint4*>(smem + SM_BL + sb) =
            *reinterpret_cast<const uint4*>(
                reinterpret_cast<const uint8_t*>(g_Wl) + srcoff * 2 + u * 16);
    }
    __syncthreads();

    const uint32_t aH = (c < 4) ? g.bAh0 : (g.bAgg + (uint32_t)(c - 4) * 16384u);
    const uint32_t aL = (c < 4) ? g.bAl0 : (aH + 8192u);

#pragma unroll
    for (int ks = 0; ks < 2; ks++) {
        const int k0 = ks * 16;
        uint32_t Ah[2][4], Al[2][4];
#pragma unroll
        for (int f = 0; f < 2; f++) {
            int row = g.warp_m * 32 + f * 16 + (g.lsub & 1) * 8 + g.lr;
            int kb  = k0 + (g.lsub >> 1) * 8;
            uint32_t ofs = sw64((uint32_t)(row * 64 + kb * 2));
            ldsm_x4(Ah[f][0], Ah[f][1], Ah[f][2], Ah[f][3], aH + ofs);
            ldsm_x4(Al[f][0], Al[f][1], Al[f][2], Al[f][3], aL + ofs);
        }
#pragma unroll
        for (int np = 0; np < 4; np++) {
            int n  = g.warp_n * 64 + np * 16 + (g.lsub >> 1) * 8 + g.lr;
            int kb = k0 + (g.lsub & 1) * 8;
            uint32_t ofs = sw64((uint32_t)(n * 64 + kb * 2));
            uint32_t Bh[4], Bl[4];
            ldsm_x4(Bh[0], Bh[1], Bh[2], Bh[3], g.bBh + ofs);
            ldsm_x4(Bl[0], Bl[1], Bl[2], Bl[3], g.bBl + ofs);
#pragma unroll
            for (int f = 0; f < 2; f++) {
                mma_bf16(acc[f][np * 2 + 0], Ah[f][0], Ah[f][1], Ah[f][2], Ah[f][3], Bh[0], Bh[1]);
                mma_bf16(acc[f][np * 2 + 1], Ah[f][0], Ah[f][1], Ah[f][2], Ah[f][3], Bh[2], Bh[3]);
                mma_bf16(acc[f][np * 2 + 0], Ah[f][0], Ah[f][1], Ah[f][2], Ah[f][3], Bl[0], Bl[1]);
                mma_bf16(acc[f][np * 2 + 1], Ah[f][0], Ah[f][1], Ah[f][2], Ah[f][3], Bl[2], Bl[3]);
                mma_bf16(acc[f][np * 2 + 0], Al[f][0], Al[f][1], Al[f][2], Al[f][3], Bh[0], Bh[1]);
                mma_bf16(acc[f][np * 2 + 1], Al[f][0], Al[f][1], Al[f][2], Al[f][3], Bh[2], Bh[3]);
            }
        }
    }
    __syncthreads();
}

__global__ void __launch_bounds__(256, 2) fused_kernel(
    const float* __restrict__ H,
    const float* __restrict__ bias,
    float* __restrict__ out)
{
    extern __shared__ __align__(16) uint8_t smem[];

    GemmCtx g;
    g.smem   = smem;
    g.H      = H;
    g.tid    = threadIdx.x;
    g.lane   = g.tid & 31;
    g.mblk   = blockIdx.x * 128;
    int wid  = g.tid >> 5;
    g.warp_m = wid >> 1;
    g.warp_n = wid & 1;
    g.lsub   = g.lane >> 3;
    g.lr     = g.lane & 7;
    g.bAh0   = smem_u32(smem + SM_AH);
    g.bAl0   = smem_u32(smem + SM_AL);
    g.bBh    = smem_u32(smem + SM_BH);
    g.bBl    = smem_u32(smem + SM_BL);
    g.bAgg   = smem_u32(smem + SM_AGG);

    float acc[2][8][4];
#pragma unroll
    for (int f = 0; f < 2; f++)
#pragma unroll
        for (int t = 0; t < 8; t++)
#pragma unroll
            for (int i = 0; i < 4; i++) acc[f][t][i] = 0.f;

    // ---- CSR-independent half first (overlaps upstream fill_adj via PDL) ----
    for (int c = 0; c < 4; c++) do_chunk(g, c, acc);

    // ---- wait for upstream kernels (g_adj) before the aggregate ----
    cudaGridDependencySynchronize();

    do_aggregate(g);
    // chunk 4's staging __syncthreads orders agg smem writes before ldsm reads

    for (int c = 4; c < 8; c++) do_chunk(g, c, acc);

    // ---- epilogue: add bias, store ----
    const int mbase = g.mblk + g.warp_m * 32 + (g.lane >> 2);
#pragma unroll
    for (int f = 0; f < 2; f++) {
        int row0 = mbase + f * 16;
        int row1 = row0 + 8;
#pragma unroll
        for (int t = 0; t < 8; t++) {
            int col = g.warp_n * 64 + t * 8 + (g.lane & 3) * 2;
            float2 bv = *reinterpret_cast<const float2*>(bias + col);
            if (row0 < N_NODES) {
                float2 o = make_float2(acc[f][t][0] + bv.x, acc[f][t][1] + bv.y);
                *reinterpret_cast<float2*>(out + (size_t)row0 * D + col) = o;
            }
            if (row1 < N_NODES) {
                float2 o = make_float2(acc[f][t][2] + bv.x, acc[f][t][3] + bv.y);
                *reinterpret_cast<float2*>(out + (size_t)row1 * D + col) = o;
            }
        }
    }
}

// ===========================================================================
// Launch (single stream; fused carries PDL attribute)
// ===========================================================================
extern "C" void kernel_launch(void* const* d_in, const int* in_sizes, int n_in,
                              void* d_out, int out_size) {
    const float* H   = (const float*)d_in[0];
    const int*   src = (const int*)d_in[1];
    const int*   dst = (const int*)d_in[2];
    const float* W   = (const float*)d_in[3];
    const float* b   = (const float*)d_in[4];
    float*       out = (float*)d_out;

    cudaFuncSetAttribute(fused_kernel,
                         cudaFuncAttributeMaxDynamicSharedMemorySize, SM_TOTAL);

    const int nb_init  = (N_NODES + 255) / 256;     // covers both init jobs
    const int nb_e8    = (N_EDGES / 8 + 255) / 256;
    const int nb_scan  = (N_NODES + 1023) / 1024;   // 98
    const int nb_gemm  = (N_NODES + 127) / 128;     // 782

    init_kernel<<<nb_init, 256>>>(W);
    hist_kernel<<<nb_e8, 256>>>(src);
    scan_partial_kernel<<<nb_scan, 1024>>>();
    scan_bsums_kernel<<<1, 128>>>(nb_scan);
    fill_adj_kernel<<<nb_e8, 256>>>(src, dst);

    // fused with programmatic dependent launch: its H-GEMM prologue may start
    // while fill_adj drains; g_adj is only read after GridDependencySynchronize
    cudaLaunchConfig_t cfg = {};
    cfg.gridDim = dim3((unsigned)nb_gemm);
    cfg.blockDim = dim3(256);
    cfg.dynamicSmemBytes = SM_TOTAL;
    cfg.stream = 0;
    cudaLaunchAttribute attrs[1];
    attrs[0].id = cudaLaunchAttributeProgrammaticStreamSerialization;
    attrs[0].val.programmaticStreamSerializationAllowed = 1;
    cfg.attrs = attrs;
    cfg.numAttrs = 1;
    cudaLaunchKernelEx(&cfg, fused_kernel, H, b, out);
}

// round 10
// speedup vs baseline: 1.0779x; 1.0514x over previous
#include <cuda_runtime.h>
#include <cuda_bf16.h>
#include <float.h>
#include <stdint.h>

#define N_NODES 100000
#define N_EDGES 1600000
#define D 128
#define KDIM 256

// ---------------------------------------------------------------------------
// Device scratch (static per harness rules).
// g_deg relies on BSS zero-init; fused_kernel re-zeros it after use so every
// graph replay starts from the same state (deterministic).
// ---------------------------------------------------------------------------
__device__ int   g_deg[N_NODES];
__device__ int   g_off[N_NODES];      // partial (pre-bsum) exclusive offsets
__device__ int   g_rank[N_EDGES];
__device__ int   g_adj[N_EDGES];
__device__ int   g_bsum[128];
__device__ int   g_bsumoff[128];
__device__ int   g_scan_ctr;          // last-block-done counter (self-resetting)

// ===========================================================================
// histogram + per-edge rank; 8 edges/thread for ILP (atomic-latency bound)
// ===========================================================================
__global__ void __launch_bounds__(256) hist_kernel(const int* __restrict__ src) {
    int i = blockIdx.x * blockDim.x + threadIdx.x;   // over E/8
    if (i < N_EDGES / 8) {
        int4 s0 = reinterpret_cast<const int4*>(src)[i * 2 + 0];
        int4 s1 = reinterpret_cast<const int4*>(src)[i * 2 + 1];
        int4 r0, r1;
        r0.x = atomicAdd(&g_deg[s0.x], 1);
        r0.y = atomicAdd(&g_deg[s0.y], 1);
        r0.z = atomicAdd(&g_deg[s0.z], 1);
        r0.w = atomicAdd(&g_deg[s0.w], 1);
        r1.x = atomicAdd(&g_deg[s1.x], 1);
        r1.y = atomicAdd(&g_deg[s1.y], 1);
        r1.z = atomicAdd(&g_deg[s1.z], 1);
        r1.w = atomicAdd(&g_deg[s1.w], 1);
        reinterpret_cast<int4*>(g_rank)[i * 2 + 0] = r0;
        reinterpret_cast<int4*>(g_rank)[i * 2 + 1] = r1;
    }
}

// ===========================================================================
// single-launch scan: warp-shuffle block scan + last-block scans the bsums
// ===========================================================================
__global__ void __launch_bounds__(1024) scan_kernel() {
    __shared__ int wsum[32];
    __shared__ int s2[128];
    __shared__ bool is_last;

    const int tid  = threadIdx.x;
    const int lane = tid & 31;
    const int wd   = tid >> 5;
    const int i    = blockIdx.x * 1024 + tid;

    int v = (i < N_NODES) ? g_deg[i] : 0;
    int x = v;
#pragma unroll
    for (int d = 1; d < 32; d <<= 1) {
        int t = __shfl_up_sync(0xffffffffu, x, d);
        if (lane >= d) x += t;
    }
    if (lane == 31) wsum[wd] = x;
    __syncthreads();
    if (wd == 0) {
        int y = wsum[lane];
#pragma unroll
        for (int d = 1; d < 32; d <<= 1) {
            int t = __shfl_up_sync(0xffffffffu, y, d);
            if (lane >= d) y += t;
        }
        wsum[lane] = y;
    }
    __syncthreads();
    int incl = x + (wd ? wsum[wd - 1] : 0);
    if (i < N_NODES) g_off[i] = incl - v;            // exclusive
    if (tid == 1023) g_bsum[blockIdx.x] = incl;      // block total

    __threadfence();
    if (tid == 0) is_last = (atomicAdd(&g_scan_ctr, 1) == (int)gridDim.x - 1);
    __syncthreads();

    if (is_last) {
        int b = (tid < 128 && tid < (int)gridDim.x) ? g_bsum[tid] : 0;
        if (tid < 128) s2[tid] = b;
        __syncthreads();
        for (int ofs = 1; ofs < 128; ofs <<= 1) {
            int t = (tid < 128 && tid >= ofs) ? s2[tid - ofs] : 0;
            __syncthreads();
            if (tid < 128) s2[tid] += t;
            __syncthreads();
        }
        if (tid < 128) g_bsumoff[tid] = s2[tid] - b; // exclusive
        if (tid == 0) g_scan_ctr = 0;                // reset for next replay
    }
}

// ===========================================================================
// atomic-free scatter; triggers dependent (fused) launch at entry (PDL)
// ===========================================================================
__global__ void __launch_bounds__(256) fill_adj_kernel(const int* __restrict__ src,
                                                       const int* __restrict__ dst) {
    asm volatile("griddepcontrol.launch_dependents;");
    int i = blockIdx.x * blockDim.x + threadIdx.x;   // over E/8
    if (i < N_EDGES / 8) {
#pragma unroll
        for (int h = 0; h < 2; h++) {
            int4 s = reinterpret_cast<const int4*>(src)[i * 2 + h];
            int4 d = reinterpret_cast<const int4*>(dst)[i * 2 + h];
            int4 r = reinterpret_cast<const int4*>(g_rank)[i * 2 + h];
            g_adj[g_off[s.x] + g_bsumoff[s.x >> 10] + r.x] = d.x;
            g_adj[g_off[s.y] + g_bsumoff[s.y >> 10] + r.y] = d.y;
            g_adj[g_off[s.z] + g_bsumoff[s.z >> 10] + r.z] = d.z;
            g_adj[g_off[s.w] + g_bsumoff[s.w >> 10] + r.w] = d.w;
        }
    }
}

// ===========================================================================
// Fused GEMM + aggregate with PDL:
//   chunks 0-3 (H@W1, no CSR dep) overlap fill_adj, then
//   cudaGridDependencySynchronize() -> aggregate -> chunks 4-7 (agg@W2).
// W is split fp32 -> bf16 hi/lo on the fly during B staging (no pre-pass).
// ===========================================================================
__device__ __forceinline__ uint32_t smem_u32(const void* p) {
    uint32_t a;
    asm("{ .reg .u64 t; cvta.to.shared.u64 t, %1; cvt.u32.u64 %0, t; }"
        : "=r"(a) : "l"(p));
    return a;
}

__device__ __forceinline__ uint32_t sw64(uint32_t b) { return b ^ ((b >> 3) & 0x30); }

__device__ __forceinline__ void ldsm_x4(uint32_t& r0, uint32_t& r1, uint32_t& r2,
                                        uint32_t& r3, uint32_t addr) {
    asm volatile("ldmatrix.sync.aligned.m8n8.x4.shared.b16 {%0,%1,%2,%3}, [%4];"
                 : "=r"(r0), "=r"(r1), "=r"(r2), "=r"(r3) : "r"(addr));
}

__device__ __forceinline__ void mma_bf16(float* c, uint32_t a0, uint32_t a1,
                                         uint32_t a2, uint32_t a3,
                                         uint32_t b0, uint32_t b1) {
    asm volatile(
        "mma.sync.aligned.m16n8k16.row.col.f32.bf16.bf16.f32 "
        "{%0,%1,%2,%3},{%4,%5,%6,%7},{%8,%9},{%0,%1,%2,%3};"
        : "+f"(c[0]), "+f"(c[1]), "+f"(c[2]), "+f"(c[3])
        : "r"(a0), "r"(a1), "r"(a2), "r"(a3), "r"(b0), "r"(b1));
}

__device__ __forceinline__ float4 max4(float4 a, float4 b) {
    return make_float4(fmaxf(a.x, b.x), fmaxf(a.y, b.y),
                       fmaxf(a.z, b.z), fmaxf(a.w, b.w));
}

__device__ __forceinline__ void split_pair(float2 v, uint32_t& hi, uint32_t& lo) {
    __nv_bfloat162 h = __float22bfloat162_rn(v);
    float2 r = make_float2(v.x - __low2float(h), v.y - __high2float(h));
    __nv_bfloat162 l = __float22bfloat162_rn(r);
    hi = *reinterpret_cast<uint32_t*>(&h);
    lo = *reinterpret_cast<uint32_t*>(&l);
}

// dynamic smem layout (96 KB total):
//   [0,      65536): aggC[4 chunks][hi 8KB | lo 8KB]
//   [65536,  73728): sAh   (H-chunk staging)
//   [73728,  81920): sAl
//   [81920,  90112): sBh
//   [90112,  98304): sBl
#define SM_AGG   0
#define SM_AH    65536
#define SM_AL    73728
#define SM_BH    81920
#define SM_BL    90112
#define SM_TOTAL 98304

struct GemmCtx {
    uint8_t* smem;
    const float* H;
    const float* W;
    int mblk, tid, lane, warp_m, warp_n, lsub, lr;
    uint32_t bAh0, bAl0, bBh, bBl, bAgg;
};

// aggregate all 16 rows per warp
__device__ __forceinline__ void do_aggregate(const GemmCtx& g) {
    const int lane = g.lane;
    const int wid  = g.tid >> 5;
    const int q  = lane & 7;
    const int ch = lane >> 3;
    uint8_t* aggHi = g.smem + SM_AGG + ch * 16384;
    uint8_t* aggLo = aggHi + 8192;
    const float* H = g.H;

    for (int i = 0; i < 16; i++) {
        int mloc  = wid * 16 + i;
        int gnode = g.mblk + mloc;
        float4 m = make_float4(-FLT_MAX, -FLT_MAX, -FLT_MAX, -FLT_MAX);
        int deg = 0;
        if (gnode < N_NODES) {
            int off = g_off[gnode] + g_bsumoff[gnode >> 10];
            deg = g_deg[gnode];
            int j = 0;
            for (; j + 8 <= deg; j += 8) {
                float4 v0 = *reinterpret_cast<const float4*>(H + (size_t)g_adj[off + j + 0] * D + lane * 4);
                float4 v1 = *reinterpret_cast<const float4*>(H + (size_t)g_adj[off + j + 1] * D + lane * 4);
                float4 v2 = *reinterpret_cast<const float4*>(H + (size_t)g_adj[off + j + 2] * D + lane * 4);
                float4 v3 = *reinterpret_cast<const float4*>(H + (size_t)g_adj[off + j + 3] * D + lane * 4);
                float4 v4 = *reinterpret_cast<const float4*>(H + (size_t)g_adj[off + j + 4] * D + lane * 4);
                float4 v5 = *reinterpret_cast<const float4*>(H + (size_t)g_adj[off + j + 5] * D + lane * 4);
                float4 v6 = *reinterpret_cast<const float4*>(H + (size_t)g_adj[off + j + 6] * D + lane * 4);
                float4 v7 = *reinterpret_cast<const float4*>(H + (size_t)g_adj[off + j + 7] * D + lane * 4);
                m = max4(m, max4(max4(max4(v0, v1), max4(v2, v3)),
                                 max4(max4(v4, v5), max4(v6, v7))));
            }
            for (; j < deg; j++) {
                m = max4(m, *reinterpret_cast<const float4*>(
                                 H + (size_t)g_adj[off + j] * D + lane * 4));
            }
        }
        if (deg == 0) m = make_float4(0.f, 0.f, 0.f, 0.f);

        uint32_t h01, l01, h23, l23;
        split_pair(make_float2(m.x, m.y), h01, l01);
        split_pair(make_float2(m.z, m.w), h23, l23);
        uint32_t sb = sw64((uint32_t)(mloc * 64 + q * 8));
        *reinterpret_cast<uint2*>(aggHi + sb) = make_uint2(h01, h23);
        *reinterpret_cast<uint2*>(aggLo + sb) = make_uint2(l01, l23);
    }
}

__device__ __forceinline__ void do_chunk(const GemmCtx& g, int c, float acc[2][8][4]) {
    const int kc = c * 32;
    uint8_t* smem = g.smem;
    const int tid = g.tid;

    // ---- stage A from H (chunks 0-3 only; 4-7 read agg smem) ----
    if (c < 4) {
#pragma unroll
        for (int i = 0; i < 4; i++) {
            int idx = i * 256 + tid;
            int m = idx >> 3, q = idx & 7;
            int gm = g.mblk + m;
            float4 v = make_float4(0.f, 0.f, 0.f, 0.f);
            if (gm < N_NODES)
                v = *reinterpret_cast<const float4*>(g.H + (size_t)gm * D + kc + q * 4);
            uint32_t h01, l01, h23, l23;
            split_pair(make_float2(v.x, v.y), h01, l01);
            split_pair(make_float2(v.z, v.w), h23, l23);
            uint32_t sb = sw64((uint32_t)(m * 64 + q * 8));
            *reinterpret_cast<uint2*>(smem + SM_AH + sb) = make_uint2(h01, h23);
            *reinterpret_cast<uint2*>(smem + SM_AL + sb) = make_uint2(l01, l23);
        }
    }

    // ---- stage B: W[n][kc..kc+32) fp32 -> bf16 hi/lo, swizzled (on the fly) ----
#pragma unroll
    for (int i = 0; i < 4; i++) {
        int idx = i * 256 + tid;
        int n = idx >> 3, q = idx & 7;
        float4 v = *reinterpret_cast<const float4*>(g.W + (size_t)n * KDIM + kc + q * 4);
        uint32_t h01, l01, h23, l23;
        split_pair(make_float2(v.x, v.y), h01, l01);
        split_pair(make_float2(v.z, v.w), h23, l23);
        uint32_t sb = sw64((uint32_t)(n * 64 + q * 8));
        *reinterpret_cast<uint2*>(smem + SM_BH + sb) = make_uint2(h01, h23);
        *reinterpret_cast<uint2*>(smem + SM_BL + sb) = make_uint2(l01, l23);
    }
    __syncthreads();

    const uint32_t aH = (c < 4) ? g.bAh0 : (g.bAgg + (uint32_t)(c - 4) * 16384u);
    const uint32_t aL = (c < 4) ? g.bAl0 : (aH + 8192u);

#pragma unroll
    for (int ks = 0; ks < 2; ks++) {
        const int k0 = ks * 16;
        uint32_t Ah[2][4], Al[2][4];
#pragma unroll
        for (int f = 0; f < 2; f++) {
            int row = g.warp_m * 32 + f * 16 + (g.lsub & 1) * 8 + g.lr;
            int kb  = k0 + (g.lsub >> 1) * 8;
            uint32_t ofs = sw64((uint32_t)(row * 64 + kb * 2));
            ldsm_x4(Ah[f][0], Ah[f][1], Ah[f][2], Ah[f][3], aH + ofs);
            ldsm_x4(Al[f][0], Al[f][1], Al[f][2], Al[f][3], aL + ofs);
        }
#pragma unroll
        for (int np = 0; np < 4; np++) {
            int n  = g.warp_n * 64 + np * 16 + (g.lsub >> 1) * 8 + g.lr;
            int kb = k0 + (g.lsub & 1) * 8;
            uint32_t ofs = sw64((uint32_t)(n * 64 + kb * 2));
            uint32_t Bh[4], Bl[4];
            ldsm_x4(Bh[0], Bh[1], Bh[2], Bh[3], g.bBh + ofs);
            ldsm_x4(Bl[0], Bl[1], Bl[2], Bl[3], g.bBl + ofs);
#pragma unroll
            for (int f = 0; f < 2; f++) {
                mma_bf16(acc[f][np * 2 + 0], Ah[f][0], Ah[f][1], Ah[f][2], Ah[f][3], Bh[0], Bh[1]);
                mma_bf16(acc[f][np * 2 + 1], Ah[f][0], Ah[f][1], Ah[f][2], Ah[f][3], Bh[2], Bh[3]);
                mma_bf16(acc[f][np * 2 + 0], Ah[f][0], Ah[f][1], Ah[f][2], Ah[f][3], Bl[0], Bl[1]);
                mma_bf16(acc[f][np * 2 + 1], Ah[f][0], Ah[f][1], Ah[f][2], Ah[f][3], Bl[2], Bl[3]);
                mma_bf16(acc[f][np * 2 + 0], Al[f][0], Al[f][1], Al[f][2], Al[f][3], Bh[0], Bh[1]);
                mma_bf16(acc[f][np * 2 + 1], Al[f][0], Al[f][1], Al[f][2], Al[f][3], Bh[2], Bh[3]);
            }
        }
    }
    __syncthreads();
}

__global__ void __launch_bounds__(256, 2) fused_kernel(
    const float* __restrict__ H,
    const float* __restrict__ W,
    const float* __restrict__ bias,
    float* __restrict__ out)
{
    extern __shared__ __align__(16) uint8_t smem[];

    GemmCtx g;
    g.smem   = smem;
    g.H      = H;
    g.W      = W;
    g.tid    = threadIdx.x;
    g.lane   = g.tid & 31;
    g.mblk   = blockIdx.x * 128;
    int wid  = g.tid >> 5;
    g.warp_m = wid >> 1;
    g.warp_n = wid & 1;
    g.lsub   = g.lane >> 3;
    g.lr     = g.lane & 7;
    g.bAh0   = smem_u32(smem + SM_AH);
    g.bAl0   = smem_u32(smem + SM_AL);
    g.bBh    = smem_u32(smem + SM_BH);
    g.bBl    = smem_u32(smem + SM_BL);
    g.bAgg   = smem_u32(smem + SM_AGG);

    float acc[2][8][4];
#pragma unroll
    for (int f = 0; f < 2; f++)
#pragma unroll
        for (int t = 0; t < 8; t++)
#pragma unroll
            for (int i = 0; i < 4; i++) acc[f][t][i] = 0.f;

    // ---- CSR-independent half first (overlaps fill_adj via PDL trigger) ----
    for (int c = 0; c < 4; c++) do_chunk(g, c, acc);

    // ---- wait for upstream kernels (g_adj) before the aggregate ----
    cudaGridDependencySynchronize();

    do_aggregate(g);
    // chunk 4's staging __syncthreads orders agg smem writes before ldsm reads

    for (int c = 4; c < 8; c++) do_chunk(g, c, acc);

    // ---- epilogue: add bias, store ----
    const int mbase = g.mblk + g.warp_m * 32 + (g.lane >> 2);
#pragma unroll
    for (int f = 0; f < 2; f++) {
        int row0 = mbase + f * 16;
        int row1 = row0 + 8;
#pragma unroll
        for (int t = 0; t < 8; t++) {
            int col = g.warp_n * 64 + t * 8 + (g.lane & 3) * 2;
            float2 bv = *reinterpret_cast<const float2*>(bias + col);
            if (row0 < N_NODES) {
                float2 o = make_float2(acc[f][t][0] + bv.x, acc[f][t][1] + bv.y);
                *reinterpret_cast<float2*>(out + (size_t)row0 * D + col) = o;
            }
            if (row1 < N_NODES) {
                float2 o = make_float2(acc[f][t][2] + bv.x, acc[f][t][3] + bv.y);
                *reinterpret_cast<float2*>(out + (size_t)row1 * D + col) = o;
            }
        }
    }

    // ---- self-restore g_deg to 0 for the next replay (deterministic) ----
    // all warps finished do_aggregate before the last do_chunk's barrier,
    // so zeroing here cannot race with any g_deg read in this CTA.
    for (int i = g.tid; i < 128; i += 256) {
        int gn = g.mblk + i;
        if (gn < N_NODES) g_deg[gn] = 0;
    }
}

// ===========================================================================
// Launch: 4 kernels, fused carries PDL attribute (trigger lives in fill_adj)
// ===========================================================================
extern "C" void kernel_launch(void* const* d_in, const int* in_sizes, int n_in,
                              void* d_out, int out_size) {
    const float* H   = (const float*)d_in[0];
    const int*   src = (const int*)d_in[1];
    const int*   dst = (const int*)d_in[2];
    const float* W   = (const float*)d_in[3];
    const float* b   = (const float*)d_in[4];
    float*       out = (float*)d_out;

    cudaFuncSetAttribute(fused_kernel,
                         cudaFuncAttributeMaxDynamicSharedMemorySize, SM_TOTAL);

    const int nb_e8   = (N_EDGES / 8 + 255) / 256;
    const int nb_scan = (N_NODES + 1023) / 1024;   // 98
    const int nb_gemm = (N_NODES + 127) / 128;     // 782

    hist_kernel<<<nb_e8, 256>>>(src);
    scan_kernel<<<nb_scan, 1024>>>();
    fill_adj_kernel<<<nb_e8, 256>>>(src, dst);

    cudaLaunchConfig_t cfg = {};
    cfg.gridDim = dim3((unsigned)nb_gemm);
    cfg.blockDim = dim3(256);
    cfg.dynamicSmemBytes = SM_TOTAL;
    cfg.stream = 0;
    cudaLaunchAttribute attrs[1];
    attrs[0].id = cudaLaunchAttributeProgrammaticStreamSerialization;
    attrs[0].val.programmaticStreamSerializationAllowed = 1;
    cfg.attrs = attrs;
    cfg.numAttrs = 1;
    cudaLaunchKernelEx(&cfg, fused_kernel, H, W, b, out);
}

// round 11
// speedup vs baseline: 1.0920x; 1.0130x over previous
#include <cuda_runtime.h>
#include <cuda_bf16.h>
#include <float.h>
#include <stdint.h>

#define N_NODES 100000
#define N_EDGES 1600000
#define D 128
#define KDIM 256

// ---------------------------------------------------------------------------
// Device scratch (static per harness rules).
// g_deg relies on BSS zero-init; fused_kernel re-zeros it after use so every
// graph replay starts from the same state (deterministic).
// ---------------------------------------------------------------------------
__device__ int   g_deg[N_NODES];
__device__ int   g_off[N_NODES];      // partial (pre-bsum) exclusive offsets
__device__ int   g_rank[N_EDGES];
__device__ int   g_adj[N_EDGES];
__device__ int   g_bsum[128];
__device__ int   g_bsumoff[128];
__device__ int   g_scan_ctr;          // last-block-done counter (self-resetting)

// ===========================================================================
// histogram + per-edge rank; 8 edges/thread for ILP (atomic-latency bound)
// ===========================================================================
__global__ void __launch_bounds__(256) hist_kernel(const int* __restrict__ src) {
    int i = blockIdx.x * blockDim.x + threadIdx.x;   // over E/8
    if (i < N_EDGES / 8) {
        int4 s0 = reinterpret_cast<const int4*>(src)[i * 2 + 0];
        int4 s1 = reinterpret_cast<const int4*>(src)[i * 2 + 1];
        int4 r0, r1;
        r0.x = atomicAdd(&g_deg[s0.x], 1);
        r0.y = atomicAdd(&g_deg[s0.y], 1);
        r0.z = atomicAdd(&g_deg[s0.z], 1);
        r0.w = atomicAdd(&g_deg[s0.w], 1);
        r1.x = atomicAdd(&g_deg[s1.x], 1);
        r1.y = atomicAdd(&g_deg[s1.y], 1);
        r1.z = atomicAdd(&g_deg[s1.z], 1);
        r1.w = atomicAdd(&g_deg[s1.w], 1);
        reinterpret_cast<int4*>(g_rank)[i * 2 + 0] = r0;
        reinterpret_cast<int4*>(g_rank)[i * 2 + 1] = r1;
    }
}

// ===========================================================================
// single-launch scan: warp-shuffle block scan + last-block scans the bsums
// ===========================================================================
__global__ void __launch_bounds__(1024) scan_kernel() {
    __shared__ int wsum[32];
    __shared__ int s2[128];
    __shared__ bool is_last;

    const int tid  = threadIdx.x;
    const int lane = tid & 31;
    const int wd   = tid >> 5;
    const int i    = blockIdx.x * 1024 + tid;

    int v = (i < N_NODES) ? g_deg[i] : 0;
    int x = v;
#pragma unroll
    for (int d = 1; d < 32; d <<= 1) {
        int t = __shfl_up_sync(0xffffffffu, x, d);
        if (lane >= d) x += t;
    }
    if (lane == 31) wsum[wd] = x;
    __syncthreads();
    if (wd == 0) {
        int y = wsum[lane];
#pragma unroll
        for (int d = 1; d < 32; d <<= 1) {
            int t = __shfl_up_sync(0xffffffffu, y, d);
            if (lane >= d) y += t;
        }
        wsum[lane] = y;
    }
    __syncthreads();
    int incl = x + (wd ? wsum[wd - 1] : 0);
    if (i < N_NODES) g_off[i] = incl - v;            // exclusive
    if (tid == 1023) g_bsum[blockIdx.x] = incl;      // block total

    __threadfence();
    if (tid == 0) is_last = (atomicAdd(&g_scan_ctr, 1) == (int)gridDim.x - 1);
    __syncthreads();

    if (is_last) {
        int b = (tid < 128 && tid < (int)gridDim.x) ? g_bsum[tid] : 0;
        if (tid < 128) s2[tid] = b;
        __syncthreads();
        for (int ofs = 1; ofs < 128; ofs <<= 1) {
            int t = (tid < 128 && tid >= ofs) ? s2[tid - ofs] : 0;
            __syncthreads();
            if (tid < 128) s2[tid] += t;
            __syncthreads();
        }
        if (tid < 128) g_bsumoff[tid] = s2[tid] - b; // exclusive
        if (tid == 0) g_scan_ctr = 0;                // reset for next replay
    }
}

// ===========================================================================
// atomic-free scatter; triggers dependent (fused) launch at entry (PDL)
// ===========================================================================
__global__ void __launch_bounds__(256) fill_adj_kernel(const int* __restrict__ src,
                                                       const int* __restrict__ dst) {
    asm volatile("griddepcontrol.launch_dependents;");
    int i = blockIdx.x * blockDim.x + threadIdx.x;   // over E/8
    if (i < N_EDGES / 8) {
#pragma unroll
        for (int h = 0; h < 2; h++) {
            int4 s = reinterpret_cast<const int4*>(src)[i * 2 + h];
            int4 d = reinterpret_cast<const int4*>(dst)[i * 2 + h];
            int4 r = reinterpret_cast<const int4*>(g_rank)[i * 2 + h];
            g_adj[g_off[s.x] + g_bsumoff[s.x >> 10] + r.x] = d.x;
            g_adj[g_off[s.y] + g_bsumoff[s.y >> 10] + r.y] = d.y;
            g_adj[g_off[s.z] + g_bsumoff[s.z >> 10] + r.z] = d.z;
            g_adj[g_off[s.w] + g_bsumoff[s.w >> 10] + r.w] = d.w;
        }
    }
}

// ===========================================================================
// Fused GEMM + aggregate, 512 threads/CTA (4x4 warp grid, warp tile 32x32):
//   chunks 0-3 (H@W1, no CSR dep) overlap fill_adj via PDL, then
//   cudaGridDependencySynchronize() -> aggregate -> chunks 4-7 (agg@W2).
// 2 CTAs/SM x 512 thr = 50% occupancy (was 22%) to hide gather latency.
// ===========================================================================
__device__ __forceinline__ uint32_t smem_u32(const void* p) {
    uint32_t a;
    asm("{ .reg .u64 t; cvta.to.shared.u64 t, %1; cvt.u32.u64 %0, t; }"
        : "=r"(a) : "l"(p));
    return a;
}

__device__ __forceinline__ uint32_t sw64(uint32_t b) { return b ^ ((b >> 3) & 0x30); }

__device__ __forceinline__ void ldsm_x4(uint32_t& r0, uint32_t& r1, uint32_t& r2,
                                        uint32_t& r3, uint32_t addr) {
    asm volatile("ldmatrix.sync.aligned.m8n8.x4.shared.b16 {%0,%1,%2,%3}, [%4];"
                 : "=r"(r0), "=r"(r1), "=r"(r2), "=r"(r3) : "r"(addr));
}

__device__ __forceinline__ void mma_bf16(float* c, uint32_t a0, uint32_t a1,
                                         uint32_t a2, uint32_t a3,
                                         uint32_t b0, uint32_t b1) {
    asm volatile(
        "mma.sync.aligned.m16n8k16.row.col.f32.bf16.bf16.f32 "
        "{%0,%1,%2,%3},{%4,%5,%6,%7},{%8,%9},{%0,%1,%2,%3};"
        : "+f"(c[0]), "+f"(c[1]), "+f"(c[2]), "+f"(c[3])
        : "r"(a0), "r"(a1), "r"(a2), "r"(a3), "r"(b0), "r"(b1));
}

__device__ __forceinline__ float4 max4(float4 a, float4 b) {
    return make_float4(fmaxf(a.x, b.x), fmaxf(a.y, b.y),
                       fmaxf(a.z, b.z), fmaxf(a.w, b.w));
}

__device__ __forceinline__ void split_pair(float2 v, uint32_t& hi, uint32_t& lo) {
    __nv_bfloat162 h = __float22bfloat162_rn(v);
    float2 r = make_float2(v.x - __low2float(h), v.y - __high2float(h));
    __nv_bfloat162 l = __float22bfloat162_rn(r);
    hi = *reinterpret_cast<uint32_t*>(&h);
    lo = *reinterpret_cast<uint32_t*>(&l);
}

// dynamic smem layout (96 KB total):
//   [0,      65536): aggC[4 chunks][hi 8KB | lo 8KB]
//   [65536,  73728): sAh   (H-chunk staging)
//   [73728,  81920): sAl
//   [81920,  90112): sBh
//   [90112,  98304): sBl
#define SM_AGG   0
#define SM_AH    65536
#define SM_AL    73728
#define SM_BH    81920
#define SM_BL    90112
#define SM_TOTAL 98304

#define NT 512

struct GemmCtx {
    uint8_t* smem;
    const float* H;
    const float* W;
    int mblk, tid, lane, warp_m, warp_n, lsub, lr;
    uint32_t bAh0, bAl0, bBh, bBl, bAgg;
};

// aggregate 8 rows per warp (16 warps x 8 rows = 128)
__device__ __forceinline__ void do_aggregate(const GemmCtx& g) {
    const int lane = g.lane;
    const int wid  = g.tid >> 5;
    const int q  = lane & 7;
    const int ch = lane >> 3;
    uint8_t* aggHi = g.smem + SM_AGG + ch * 16384;
    uint8_t* aggLo = aggHi + 8192;
    const float* H = g.H;

    for (int i = 0; i < 8; i++) {
        int mloc  = wid * 8 + i;
        int gnode = g.mblk + mloc;
        float4 m = make_float4(-FLT_MAX, -FLT_MAX, -FLT_MAX, -FLT_MAX);
        int deg = 0;
        if (gnode < N_NODES) {
            int off = g_off[gnode] + g_bsumoff[gnode >> 10];
            deg = g_deg[gnode];
            int j = 0;
            for (; j + 8 <= deg; j += 8) {
                float4 v0 = *reinterpret_cast<const float4*>(H + (size_t)g_adj[off + j + 0] * D + lane * 4);
                float4 v1 = *reinterpret_cast<const float4*>(H + (size_t)g_adj[off + j + 1] * D + lane * 4);
                float4 v2 = *reinterpret_cast<const float4*>(H + (size_t)g_adj[off + j + 2] * D + lane * 4);
                float4 v3 = *reinterpret_cast<const float4*>(H + (size_t)g_adj[off + j + 3] * D + lane * 4);
                float4 v4 = *reinterpret_cast<const float4*>(H + (size_t)g_adj[off + j + 4] * D + lane * 4);
                float4 v5 = *reinterpret_cast<const float4*>(H + (size_t)g_adj[off + j + 5] * D + lane * 4);
                float4 v6 = *reinterpret_cast<const float4*>(H + (size_t)g_adj[off + j + 6] * D + lane * 4);
                float4 v7 = *reinterpret_cast<const float4*>(H + (size_t)g_adj[off + j + 7] * D + lane * 4);
                m = max4(m, max4(max4(max4(v0, v1), max4(v2, v3)),
                                 max4(max4(v4, v5), max4(v6, v7))));
            }
            for (; j < deg; j++) {
                m = max4(m, *reinterpret_cast<const float4*>(
                                 H + (size_t)g_adj[off + j] * D + lane * 4));
            }
        }
        if (deg == 0) m = make_float4(0.f, 0.f, 0.f, 0.f);

        uint32_t h01, l01, h23, l23;
        split_pair(make_float2(m.x, m.y), h01, l01);
        split_pair(make_float2(m.z, m.w), h23, l23);
        uint32_t sb = sw64((uint32_t)(mloc * 64 + q * 8));
        *reinterpret_cast<uint2*>(aggHi + sb) = make_uint2(h01, h23);
        *reinterpret_cast<uint2*>(aggLo + sb) = make_uint2(l01, l23);
    }
}

__device__ __forceinline__ void do_chunk(const GemmCtx& g, int c, float acc[2][4][4]) {
    const int kc = c * 32;
    uint8_t* smem = g.smem;
    const int tid = g.tid;

    // ---- stage A from H (chunks 0-3 only; 4-7 read agg smem) ----
    if (c < 4) {
#pragma unroll
        for (int i = 0; i < 2; i++) {
            int idx = i * NT + tid;
            int m = idx >> 3, q = idx & 7;
            int gm = g.mblk + m;
            float4 v = make_float4(0.f, 0.f, 0.f, 0.f);
            if (gm < N_NODES)
                v = *reinterpret_cast<const float4*>(g.H + (size_t)gm * D + kc + q * 4);
            uint32_t h01, l01, h23, l23;
            split_pair(make_float2(v.x, v.y), h01, l01);
            split_pair(make_float2(v.z, v.w), h23, l23);
            uint32_t sb = sw64((uint32_t)(m * 64 + q * 8));
            *reinterpret_cast<uint2*>(smem + SM_AH + sb) = make_uint2(h01, h23);
            *reinterpret_cast<uint2*>(smem + SM_AL + sb) = make_uint2(l01, l23);
        }
    }

    // ---- stage B: W[n][kc..kc+32) fp32 -> bf16 hi/lo, swizzled (on the fly) ----
#pragma unroll
    for (int i = 0; i < 2; i++) {
        int idx = i * NT + tid;
        int n = idx >> 3, q = idx & 7;
        float4 v = *reinterpret_cast<const float4*>(g.W + (size_t)n * KDIM + kc + q * 4);
        uint32_t h01, l01, h23, l23;
        split_pair(make_float2(v.x, v.y), h01, l01);
        split_pair(make_float2(v.z, v.w), h23, l23);
        uint32_t sb = sw64((uint32_t)(n * 64 + q * 8));
        *reinterpret_cast<uint2*>(smem + SM_BH + sb) = make_uint2(h01, h23);
        *reinterpret_cast<uint2*>(smem + SM_BL + sb) = make_uint2(l01, l23);
    }
    __syncthreads();

    const uint32_t aH = (c < 4) ? g.bAh0 : (g.bAgg + (uint32_t)(c - 4) * 16384u);
    const uint32_t aL = (c < 4) ? g.bAl0 : (aH + 8192u);

#pragma unroll
    for (int ks = 0; ks < 2; ks++) {
        const int k0 = ks * 16;
        uint32_t Ah[2][4], Al[2][4];
#pragma unroll
        for (int f = 0; f < 2; f++) {
            int row = g.warp_m * 32 + f * 16 + (g.lsub & 1) * 8 + g.lr;
            int kb  = k0 + (g.lsub >> 1) * 8;
            uint32_t ofs = sw64((uint32_t)(row * 64 + kb * 2));
            ldsm_x4(Ah[f][0], Ah[f][1], Ah[f][2], Ah[f][3], aH + ofs);
            ldsm_x4(Al[f][0], Al[f][1], Al[f][2], Al[f][3], aL + ofs);
        }
#pragma unroll
        for (int np = 0; np < 2; np++) {
            int n  = g.warp_n * 32 + np * 16 + (g.lsub >> 1) * 8 + g.lr;
            int kb = k0 + (g.lsub & 1) * 8;
            uint32_t ofs = sw64((uint32_t)(n * 64 + kb * 2));
            uint32_t Bh[4], Bl[4];
            ldsm_x4(Bh[0], Bh[1], Bh[2], Bh[3], g.bBh + ofs);
            ldsm_x4(Bl[0], Bl[1], Bl[2], Bl[3], g.bBl + ofs);
#pragma unroll
            for (int f = 0; f < 2; f++) {
                mma_bf16(acc[f][np * 2 + 0], Ah[f][0], Ah[f][1], Ah[f][2], Ah[f][3], Bh[0], Bh[1]);
                mma_bf16(acc[f][np * 2 + 1], Ah[f][0], Ah[f][1], Ah[f][2], Ah[f][3], Bh[2], Bh[3]);
                mma_bf16(acc[f][np * 2 + 0], Ah[f][0], Ah[f][1], Ah[f][2], Ah[f][3], Bl[0], Bl[1]);
                mma_bf16(acc[f][np * 2 + 1], Ah[f][0], Ah[f][1], Ah[f][2], Ah[f][3], Bl[2], Bl[3]);
                mma_bf16(acc[f][np * 2 + 0], Al[f][0], Al[f][1], Al[f][2], Al[f][3], Bh[0], Bh[1]);
                mma_bf16(acc[f][np * 2 + 1], Al[f][0], Al[f][1], Al[f][2], Al[f][3], Bh[2], Bh[3]);
            }
        }
    }
    __syncthreads();
}

__global__ void __launch_bounds__(NT, 2) fused_kernel(
    const float* __restrict__ H,
    const float* __restrict__ W,
    const float* __restrict__ bias,
    float* __restrict__ out)
{
    extern __shared__ __align__(16) uint8_t smem[];

    GemmCtx g;
    g.smem   = smem;
    g.H      = H;
    g.W      = W;
    g.tid    = threadIdx.x;
    g.lane   = g.tid & 31;
    g.mblk   = blockIdx.x * 128;
    int wid  = g.tid >> 5;
    g.warp_m = wid >> 2;      // 0..3
    g.warp_n = wid & 3;       // 0..3
    g.lsub   = g.lane >> 3;
    g.lr     = g.lane & 7;
    g.bAh0   = smem_u32(smem + SM_AH);
    g.bAl0   = smem_u32(smem + SM_AL);
    g.bBh    = smem_u32(smem + SM_BH);
    g.bBl    = smem_u32(smem + SM_BL);
    g.bAgg   = smem_u32(smem + SM_AGG);

    float acc[2][4][4];
#pragma unroll
    for (int f = 0; f < 2; f++)
#pragma unroll
        for (int t = 0; t < 4; t++)
#pragma unroll
            for (int i = 0; i < 4; i++) acc[f][t][i] = 0.f;

    // ---- CSR-independent half first (overlaps fill_adj via PDL trigger) ----
    for (int c = 0; c < 4; c++) do_chunk(g, c, acc);

    // ---- wait for upstream kernels (g_adj) before the aggregate ----
    cudaGridDependencySynchronize();

    do_aggregate(g);
    // chunk 4's staging __syncthreads orders agg smem writes before ldsm reads

    for (int c = 4; c < 8; c++) do_chunk(g, c, acc);

    // ---- epilogue: add bias, store ----
    const int mbase = g.mblk + g.warp_m * 32 + (g.lane >> 2);
#pragma unroll
    for (int f = 0; f < 2; f++) {
        int row0 = mbase + f * 16;
        int row1 = row0 + 8;
#pragma unroll
        for (int t = 0; t < 4; t++) {
            int col = g.warp_n * 32 + t * 8 + (g.lane & 3) * 2;
            float2 bv = *reinterpret_cast<const float2*>(bias + col);
            if (row0 < N_NODES) {
                float2 o = make_float2(acc[f][t][0] + bv.x, acc[f][t][1] + bv.y);
                *reinterpret_cast<float2*>(out + (size_t)row0 * D + col) = o;
            }
            if (row1 < N_NODES) {
                float2 o = make_float2(acc[f][t][2] + bv.x, acc[f][t][3] + bv.y);
                *reinterpret_cast<float2*>(out + (size_t)row1 * D + col) = o;
            }
        }
    }

    // ---- self-restore g_deg to 0 for the next replay (deterministic) ----
    for (int i = g.tid; i < 128; i += NT) {
        int gn = g.mblk + i;
        if (gn < N_NODES) g_deg[gn] = 0;
    }
}

// ===========================================================================
// Launch: 4 kernels, fused carries PDL attribute (trigger lives in fill_adj)
// ===========================================================================
extern "C" void kernel_launch(void* const* d_in, const int* in_sizes, int n_in,
                              void* d_out, int out_size) {
    const float* H   = (const float*)d_in[0];
    const int*   src = (const int*)d_in[1];
    const int*   dst = (const int*)d_in[2];
    const float* W   = (const float*)d_in[3];
    const float* b   = (const float*)d_in[4];
    float*       out = (float*)d_out;

    cudaFuncSetAttribute(fused_kernel,
                         cudaFuncAttributeMaxDynamicSharedMemorySize, SM_TOTAL);

    const int nb_e8   = (N_EDGES / 8 + 255) / 256;
    const int nb_scan = (N_NODES + 1023) / 1024;   // 98
    const int nb_gemm = (N_NODES + 127) / 128;     // 782

    hist_kernel<<<nb_e8, 256>>>(src);
    scan_kernel<<<nb_scan, 1024>>>();
    fill_adj_kernel<<<nb_e8, 256>>>(src, dst);

    cudaLaunchConfig_t cfg = {};
    cfg.gridDim = dim3((unsigned)nb_gemm);
    cfg.blockDim = dim3(NT);
    cfg.dynamicSmemBytes = SM_TOTAL;
    cfg.stream = 0;
    cudaLaunchAttribute attrs[1];
    attrs[0].id = cudaLaunchAttributeProgrammaticStreamSerialization;
    attrs[0].val.programmaticStreamSerializationAllowed = 1;
    cfg.attrs = attrs;
    cfg.numAttrs = 1;
    cudaLaunchKernelEx(&cfg, fused_kernel, H, W, b, out);
}

// round 13
// speedup vs baseline: 1.2089x; 1.1071x over previous
#include <cuda_runtime.h>
#include <cuda_bf16.h>
#include <cuda_fp16.h>
#include <float.h>
#include <stdint.h>

#define N_NODES 100000
#define N_EDGES 1600000
#define D 128
#define KDIM 256

// ---------------------------------------------------------------------------
// Device scratch (static per harness rules).
// g_deg relies on BSS zero-init; fused_kernel re-zeros it after use.
// ---------------------------------------------------------------------------
__device__ int   g_deg[N_NODES];
__device__ int   g_off[N_NODES];
__device__ int   g_rank[N_EDGES];
__device__ int   g_adj[N_EDGES];
__device__ int   g_bsum[128];
__device__ int   g_bsumoff[128];
__device__ int   g_scan_ctr;
__device__ __align__(16) __half g_Hh[(size_t)N_NODES * D];  // fp16 copy of H

// ===========================================================================
// hist + H->fp16 conversion in ONE kernel (block-range split)
// ===========================================================================
#define NB_HIST 782                        // ceil(200000/256)
#define NB_CONV 6250                       // 12.8M elems / 8 per thread / 256

__global__ void __launch_bounds__(256) hist_conv_kernel(const int* __restrict__ src,
                                                        const float* __restrict__ H) {
    if (blockIdx.x < NB_HIST) {
        int i = blockIdx.x * blockDim.x + threadIdx.x;   // over E/8
        if (i < N_EDGES / 8) {
            int4 s0 = reinterpret_cast<const int4*>(src)[i * 2 + 0];
            int4 s1 = reinterpret_cast<const int4*>(src)[i * 2 + 1];
            int4 r0, r1;
            r0.x = atomicAdd(&g_deg[s0.x], 1);
            r0.y = atomicAdd(&g_deg[s0.y], 1);
            r0.z = atomicAdd(&g_deg[s0.z], 1);
            r0.w = atomicAdd(&g_deg[s0.w], 1);
            r1.x = atomicAdd(&g_deg[s1.x], 1);
            r1.y = atomicAdd(&g_deg[s1.y], 1);
            r1.z = atomicAdd(&g_deg[s1.z], 1);
            r1.w = atomicAdd(&g_deg[s1.w], 1);
            reinterpret_cast<int4*>(g_rank)[i * 2 + 0] = r0;
            reinterpret_cast<int4*>(g_rank)[i * 2 + 1] = r1;
        }
    } else {
        size_t j = (size_t)(blockIdx.x - NB_HIST) * blockDim.x + threadIdx.x;
        size_t base = j * 8;
        if (base < (size_t)N_NODES * D) {
            float4 a = *reinterpret_cast<const float4*>(H + base);
            float4 b = *reinterpret_cast<const float4*>(H + base + 4);
            __half2 p0 = __float22half2_rn(make_float2(a.x, a.y));
            __half2 p1 = __float22half2_rn(make_float2(a.z, a.w));
            __half2 p2 = __float22half2_rn(make_float2(b.x, b.y));
            __half2 p3 = __float22half2_rn(make_float2(b.z, b.w));
            uint4 o;
            o.x = *reinterpret_cast<uint32_t*>(&p0);
            o.y = *reinterpret_cast<uint32_t*>(&p1);
            o.z = *reinterpret_cast<uint32_t*>(&p2);
            o.w = *reinterpret_cast<uint32_t*>(&p3);
            *reinterpret_cast<uint4*>(reinterpret_cast<uint8_t*>(g_Hh) + base * 2) = o;
        }
    }
}

// ===========================================================================
// single-launch scan: warp-shuffle block scan + last-block scans the bsums
// ===========================================================================
__global__ void __launch_bounds__(1024) scan_kernel() {
    __shared__ int wsum[32];
    __shared__ int s2[128];
    __shared__ bool is_last;

    const int tid  = threadIdx.x;
    const int lane = tid & 31;
    const int wd   = tid >> 5;
    const int i    = blockIdx.x * 1024 + tid;

    int v = (i < N_NODES) ? g_deg[i] : 0;
    int x = v;
#pragma unroll
    for (int d = 1; d < 32; d <<= 1) {
        int t = __shfl_up_sync(0xffffffffu, x, d);
        if (lane >= d) x += t;
    }
    if (lane == 31) wsum[wd] = x;
    __syncthreads();
    if (wd == 0) {
        int y = wsum[lane];
#pragma unroll
        for (int d = 1; d < 32; d <<= 1) {
            int t = __shfl_up_sync(0xffffffffu, y, d);
            if (lane >= d) y += t;
        }
        wsum[lane] = y;
    }
    __syncthreads();
    int incl = x + (wd ? wsum[wd - 1] : 0);
    if (i < N_NODES) g_off[i] = incl - v;
    if (tid == 1023) g_bsum[blockIdx.x] = incl;

    __threadfence();
    if (tid == 0) is_last = (atomicAdd(&g_scan_ctr, 1) == (int)gridDim.x - 1);
    __syncthreads();

    if (is_last) {
        int b = (tid < 128 && tid < (int)gridDim.x) ? g_bsum[tid] : 0;
        if (tid < 128) s2[tid] = b;
        __syncthreads();
        for (int ofs = 1; ofs < 128; ofs <<= 1) {
            int t = (tid < 128 && tid >= ofs) ? s2[tid - ofs] : 0;
            __syncthreads();
            if (tid < 128) s2[tid] += t;
            __syncthreads();
        }
        if (tid < 128) g_bsumoff[tid] = s2[tid] - b;
        if (tid == 0) g_scan_ctr = 0;
    }
}

// ===========================================================================
// atomic-free scatter; triggers dependent (fused) launch at entry (PDL)
// ===========================================================================
__global__ void __launch_bounds__(256) fill_adj_kernel(const int* __restrict__ src,
                                                       const int* __restrict__ dst) {
    asm volatile("griddepcontrol.launch_dependents;");
    int i = blockIdx.x * blockDim.x + threadIdx.x;
    if (i < N_EDGES / 8) {
#pragma unroll
        for (int h = 0; h < 2; h++) {
            int4 s = reinterpret_cast<const int4*>(src)[i * 2 + h];
            int4 d = reinterpret_cast<const int4*>(dst)[i * 2 + h];
            int4 r = reinterpret_cast<const int4*>(g_rank)[i * 2 + h];
            g_adj[g_off[s.x] + g_bsumoff[s.x >> 10] + r.x] = d.x;
            g_adj[g_off[s.y] + g_bsumoff[s.y >> 10] + r.y] = d.y;
            g_adj[g_off[s.z] + g_bsumoff[s.z >> 10] + r.z] = d.z;
            g_adj[g_off[s.w] + g_bsumoff[s.w >> 10] + r.w] = d.w;
        }
    }
}

// ===========================================================================
// Fused GEMM + aggregate, 512 threads (4x4 warp grid, warp tile 32x32).
// Aggregate gathers FP16 rows (half the bytes/L1-wavefronts of fp32); the
// fp16 max result is split EXACTLY into bf16 hi/lo (11-bit significand fits),
// so agg chunks use the same 3-pass MMA as H chunks.
// ===========================================================================
__device__ __forceinline__ uint32_t smem_u32(const void* p) {
    uint32_t a;
    asm("{ .reg .u64 t; cvta.to.shared.u64 t, %1; cvt.u32.u64 %0, t; }"
        : "=r"(a) : "l"(p));
    return a;
}

__device__ __forceinline__ uint32_t sw64(uint32_t b) { return b ^ ((b >> 3) & 0x30); }

__device__ __forceinline__ void ldsm_x4(uint32_t& r0, uint32_t& r1, uint32_t& r2,
                                        uint32_t& r3, uint32_t addr) {
    asm volatile("ldmatrix.sync.aligned.m8n8.x4.shared.b16 {%0,%1,%2,%3}, [%4];"
                 : "=r"(r0), "=r"(r1), "=r"(r2), "=r"(r3) : "r"(addr));
}

__device__ __forceinline__ void mma_bf16(float* c, uint32_t a0, uint32_t a1,
                                         uint32_t a2, uint32_t a3,
                                         uint32_t b0, uint32_t b1) {
    asm volatile(
        "mma.sync.aligned.m16n8k16.row.col.f32.bf16.bf16.f32 "
        "{%0,%1,%2,%3},{%4,%5,%6,%7},{%8,%9},{%0,%1,%2,%3};"
        : "+f"(c[0]), "+f"(c[1]), "+f"(c[2]), "+f"(c[3])
        : "r"(a0), "r"(a1), "r"(a2), "r"(a3), "r"(b0), "r"(b1));
}

__device__ __forceinline__ void split_pair(float2 v, uint32_t& hi, uint32_t& lo) {
    __nv_bfloat162 h = __float22bfloat162_rn(v);
    float2 r = make_float2(v.x - __low2float(h), v.y - __high2float(h));
    __nv_bfloat162 l = __float22bfloat162_rn(r);
    hi = *reinterpret_cast<uint32_t*>(&h);
    lo = *reinterpret_cast<uint32_t*>(&l);
}

__device__ __forceinline__ void hmax2_acc(uint2& m, uint2 v) {
    __half2 ma = *reinterpret_cast<__half2*>(&m.x);
    __half2 mb = *reinterpret_cast<__half2*>(&m.y);
    ma = __hmax2(ma, *reinterpret_cast<const __half2*>(&v.x));
    mb = __hmax2(mb, *reinterpret_cast<const __half2*>(&v.y));
    m.x = *reinterpret_cast<uint32_t*>(&ma);
    m.y = *reinterpret_cast<uint32_t*>(&mb);
}

// dynamic smem layout (96 KB total):
//   [0,      65536): aggC[4 chunks][hi 8KB | lo 8KB]
//   [65536,  73728): sAh
//   [73728,  81920): sAl
//   [81920,  90112): sBh
//   [90112,  98304): sBl
#define SM_AGG   0
#define SM_AH    65536
#define SM_AL    73728
#define SM_BH    81920
#define SM_BL    90112
#define SM_TOTAL 98304

#define NT 512

struct GemmCtx {
    uint8_t* smem;
    const float* H;
    const float* W;
    int mblk, tid, lane, warp_m, warp_n, lsub, lr;
    uint32_t bAh0, bAl0, bBh, bBl, bAgg;
};

// aggregate 8 rows per warp from fp16 H copy; one uint2 (4 halves) per lane
__device__ __forceinline__ void do_aggregate(const GemmCtx& g) {
    const int lane = g.lane;
    const int wid  = g.tid >> 5;
    const int q  = lane & 7;
    const int ch = lane >> 3;
    uint8_t* aggHi = g.smem + SM_AGG + ch * 16384;
    uint8_t* aggLo = aggHi + 8192;

    const uint8_t* Hh = reinterpret_cast<const uint8_t*>(g_Hh);
    const uint32_t lane_off = (uint32_t)lane * 8;    // bytes within 256B row

    const uint32_t NEGINF2 = 0xFC00FC00u;            // -inf fp16 x2

    for (int i = 0; i < 8; i++) {
        int mloc  = wid * 8 + i;
        int gnode = g.mblk + mloc;
        uint2 m = make_uint2(NEGINF2, NEGINF2);
        int deg = 0;
        if (gnode < N_NODES) {
            int off = g_off[gnode] + g_bsumoff[gnode >> 10];
            deg = g_deg[gnode];
            int j = 0;
            for (; j + 8 <= deg; j += 8) {
                uint2 v0 = *reinterpret_cast<const uint2*>(Hh + (size_t)g_adj[off + j + 0] * 256 + lane_off);
                uint2 v1 = *reinterpret_cast<const uint2*>(Hh + (size_t)g_adj[off + j + 1] * 256 + lane_off);
                uint2 v2 = *reinterpret_cast<const uint2*>(Hh + (size_t)g_adj[off + j + 2] * 256 + lane_off);
                uint2 v3 = *reinterpret_cast<const uint2*>(Hh + (size_t)g_adj[off + j + 3] * 256 + lane_off);
                uint2 v4 = *reinterpret_cast<const uint2*>(Hh + (size_t)g_adj[off + j + 4] * 256 + lane_off);
                uint2 v5 = *reinterpret_cast<const uint2*>(Hh + (size_t)g_adj[off + j + 5] * 256 + lane_off);
                uint2 v6 = *reinterpret_cast<const uint2*>(Hh + (size_t)g_adj[off + j + 6] * 256 + lane_off);
                uint2 v7 = *reinterpret_cast<const uint2*>(Hh + (size_t)g_adj[off + j + 7] * 256 + lane_off);
                hmax2_acc(m, v0); hmax2_acc(m, v1); hmax2_acc(m, v2); hmax2_acc(m, v3);
                hmax2_acc(m, v4); hmax2_acc(m, v5); hmax2_acc(m, v6); hmax2_acc(m, v7);
            }
            for (; j < deg; j++) {
                uint2 v = *reinterpret_cast<const uint2*>(Hh + (size_t)g_adj[off + j] * 256 + lane_off);
                hmax2_acc(m, v);
            }
        }

        float2 f01, f23;
        if (deg == 0) {
            f01 = make_float2(0.f, 0.f);
            f23 = make_float2(0.f, 0.f);
        } else {
            f01 = __half22float2(*reinterpret_cast<__half2*>(&m.x));
            f23 = __half22float2(*reinterpret_cast<__half2*>(&m.y));
        }
        uint32_t h01, l01, h23, l23;
        split_pair(f01, h01, l01);   // exact: fp16 -> bf16 hi + bf16 lo
        split_pair(f23, h23, l23);
        uint32_t sb = sw64((uint32_t)(mloc * 64 + q * 8));
        *reinterpret_cast<uint2*>(aggHi + sb) = make_uint2(h01, h23);
        *reinterpret_cast<uint2*>(aggLo + sb) = make_uint2(l01, l23);
    }
}

__device__ __forceinline__ void do_chunk(const GemmCtx& g, int c, float acc[2][4][4]) {
    const int kc = c * 32;
    uint8_t* smem = g.smem;
    const int tid = g.tid;

    // ---- stage A from H (chunks 0-3 only; 4-7 read agg smem) ----
    if (c < 4) {
#pragma unroll
        for (int i = 0; i < 2; i++) {
            int idx = i * NT + tid;
            int m = idx >> 3, q = idx & 7;
            int gm = g.mblk + m;
            float4 v = make_float4(0.f, 0.f, 0.f, 0.f);
            if (gm < N_NODES)
                v = *reinterpret_cast<const float4*>(g.H + (size_t)gm * D + kc + q * 4);
            uint32_t h01, l01, h23, l23;
            split_pair(make_float2(v.x, v.y), h01, l01);
            split_pair(make_float2(v.z, v.w), h23, l23);
            uint32_t sb = sw64((uint32_t)(m * 64 + q * 8));
            *reinterpret_cast<uint2*>(smem + SM_AH + sb) = make_uint2(h01, h23);
            *reinterpret_cast<uint2*>(smem + SM_AL + sb) = make_uint2(l01, l23);
        }
    }

    // ---- stage B: W[n][kc..kc+32) fp32 -> bf16 hi/lo, swizzled ----
#pragma unroll
    for (int i = 0; i < 2; i++) {
        int idx = i * NT + tid;
        int n = idx >> 3, q = idx & 7;
        float4 v = *reinterpret_cast<const float4*>(g.W + (size_t)n * KDIM + kc + q * 4);
        uint32_t h01, l01, h23, l23;
        split_pair(make_float2(v.x, v.y), h01, l01);
        split_pair(make_float2(v.z, v.w), h23, l23);
        uint32_t sb = sw64((uint32_t)(n * 64 + q * 8));
        *reinterpret_cast<uint2*>(smem + SM_BH + sb) = make_uint2(h01, h23);
        *reinterpret_cast<uint2*>(smem + SM_BL + sb) = make_uint2(l01, l23);
    }
    __syncthreads();

    const uint32_t aH = (c < 4) ? g.bAh0 : (g.bAgg + (uint32_t)(c - 4) * 16384u);
    const uint32_t aL = (c < 4) ? g.bAl0 : (aH + 8192u);

#pragma unroll
    for (int ks = 0; ks < 2; ks++) {
        const int k0 = ks * 16;
        uint32_t Ah[2][4], Al[2][4];
#pragma unroll
        for (int f = 0; f < 2; f++) {
            int row = g.warp_m * 32 + f * 16 + (g.lsub & 1) * 8 + g.lr;
            int kb  = k0 + (g.lsub >> 1) * 8;
            uint32_t ofs = sw64((uint32_t)(row * 64 + kb * 2));
            ldsm_x4(Ah[f][0], Ah[f][1], Ah[f][2], Ah[f][3], aH + ofs);
            ldsm_x4(Al[f][0], Al[f][1], Al[f][2], Al[f][3], aL + ofs);
        }
#pragma unroll
        for (int np = 0; np < 2; np++) {
            int n  = g.warp_n * 32 + np * 16 + (g.lsub >> 1) * 8 + g.lr;
            int kb = k0 + (g.lsub & 1) * 8;
            uint32_t ofs = sw64((uint32_t)(n * 64 + kb * 2));
            uint32_t Bh[4], Bl[4];
            ldsm_x4(Bh[0], Bh[1], Bh[2], Bh[3], g.bBh + ofs);
            ldsm_x4(Bl[0], Bl[1], Bl[2], Bl[3], g.bBl + ofs);
#pragma unroll
            for (int f = 0; f < 2; f++) {
                mma_bf16(acc[f][np * 2 + 0], Ah[f][0], Ah[f][1], Ah[f][2], Ah[f][3], Bh[0], Bh[1]);
                mma_bf16(acc[f][np * 2 + 1], Ah[f][0], Ah[f][1], Ah[f][2], Ah[f][3], Bh[2], Bh[3]);
                mma_bf16(acc[f][np * 2 + 0], Ah[f][0], Ah[f][1], Ah[f][2], Ah[f][3], Bl[0], Bl[1]);
                mma_bf16(acc[f][np * 2 + 1], Ah[f][0], Ah[f][1], Ah[f][2], Ah[f][3], Bl[2], Bl[3]);
                mma_bf16(acc[f][np * 2 + 0], Al[f][0], Al[f][1], Al[f][2], Al[f][3], Bh[0], Bh[1]);
                mma_bf16(acc[f][np * 2 + 1], Al[f][0], Al[f][1], Al[f][2], Al[f][3], Bh[2], Bh[3]);
            }
        }
    }
    __syncthreads();
}

__global__ void __launch_bounds__(NT, 2) fused_kernel(
    const float* __restrict__ H,
    const float* __restrict__ W,
    const float* __restrict__ bias,
    float* __restrict__ out)
{
    extern __shared__ __align__(16) uint8_t smem[];

    GemmCtx g;
    g.smem   = smem;
    g.H      = H;
    g.W      = W;
    g.tid    = threadIdx.x;
    g.lane   = g.tid & 31;
    g.mblk   = blockIdx.x * 128;
    int wid  = g.tid >> 5;
    g.warp_m = wid >> 2;
    g.warp_n = wid & 3;
    g.lsub   = g.lane >> 3;
    g.lr     = g.lane & 7;
    g.bAh0   = smem_u32(smem + SM_AH);
    g.bAl0   = smem_u32(smem + SM_AL);
    g.bBh    = smem_u32(smem + SM_BH);
    g.bBl    = smem_u32(smem + SM_BL);
    g.bAgg   = smem_u32(smem + SM_AGG);

    float acc[2][4][4];
#pragma unroll
    for (int f = 0; f < 2; f++)
#pragma unroll
        for (int t = 0; t < 4; t++)
#pragma unroll
            for (int i = 0; i < 4; i++) acc[f][t][i] = 0.f;

    // ---- CSR-independent half first (overlaps fill_adj via PDL trigger) ----
    for (int c = 0; c < 4; c++) do_chunk(g, c, acc);

    // ---- wait for upstream kernels (g_adj) before the aggregate ----
    cudaGridDependencySynchronize();

    do_aggregate(g);
    // chunk 4's staging __syncthreads orders agg smem writes before ldsm reads

    for (int c = 4; c < 8; c++) do_chunk(g, c, acc);

    // ---- epilogue: add bias, store ----
    const int mbase = g.mblk + g.warp_m * 32 + (g.lane >> 2);
#pragma unroll
    for (int f = 0; f < 2; f++) {
        int row0 = mbase + f * 16;
        int row1 = row0 + 8;
#pragma unroll
        for (int t = 0; t < 4; t++) {
            int col = g.warp_n * 32 + t * 8 + (g.lane & 3) * 2;
            float2 bv = *reinterpret_cast<const float2*>(bias + col);
            if (row0 < N_NODES) {
                float2 o = make_float2(acc[f][t][0] + bv.x, acc[f][t][1] + bv.y);
                *reinterpret_cast<float2*>(out + (size_t)row0 * D + col) = o;
            }
            if (row1 < N_NODES) {
                float2 o = make_float2(acc[f][t][2] + bv.x, acc[f][t][3] + bv.y);
                *reinterpret_cast<float2*>(out + (size_t)row1 * D + col) = o;
            }
        }
    }

    // ---- self-restore g_deg to 0 for the next replay (deterministic) ----
    for (int i = g.tid; i < 128; i += NT) {
        int gn = g.mblk + i;
        if (gn < N_NODES) g_deg[gn] = 0;
    }
}

// ===========================================================================
// Launch: 3 prologue kernels + fused (PDL trigger lives in fill_adj)
// ===========================================================================
extern "C" void kernel_launch(void* const* d_in, const int* in_sizes, int n_in,
                              void* d_out, int out_size) {
    const float* H   = (const float*)d_in[0];
    const int*   src = (const int*)d_in[1];
    const int*   dst = (const int*)d_in[2];
    const float* W   = (const float*)d_in[3];
    const float* b   = (const float*)d_in[4];
    float*       out = (float*)d_out;

    cudaFuncSetAttribute(fused_kernel,
                         cudaFuncAttributeMaxDynamicSharedMemorySize, SM_TOTAL);

    const int nb_scan = (N_NODES + 1023) / 1024;   // 98
    const int nb_gemm = (N_NODES + 127) / 128;     // 782
    const int nb_e8   = (N_EDGES / 8 + 255) / 256; // 782

    hist_conv_kernel<<<NB_HIST + NB_CONV, 256>>>(src, H);
    scan_kernel<<<nb_scan, 1024>>>();
    fill_adj_kernel<<<nb_e8, 256>>>(src, dst);

    cudaLaunchConfig_t cfg = {};
    cfg.gridDim = dim3((unsigned)nb_gemm);
    cfg.blockDim = dim3(NT);
    cfg.dynamicSmemBytes = SM_TOTAL;
    cfg.stream = 0;
    cudaLaunchAttribute attrs[1];
    attrs[0].id = cudaLaunchAttributeProgrammaticStreamSerialization;
    attrs[0].val.programmaticStreamSerializationAllowed = 1;
    cfg.attrs = attrs;
    cfg.numAttrs = 1;
    cudaLaunchKernelEx(&cfg, fused_kernel, H, W, b, out);
}

// round 14
// speedup vs baseline: 1.4114x; 1.1675x over previous
#include <cuda_runtime.h>
#include <cuda_bf16.h>
#include <cuda_fp16.h>
#include <float.h>
#include <stdint.h>

#define N_NODES 100000
#define N_EDGES 1600000
#define D 128
#define KDIM 256

// ---------------------------------------------------------------------------
// Device scratch (static per harness rules).
// g_deg relies on BSS zero-init; fused_kernel re-zeros it after use.
// ---------------------------------------------------------------------------
__device__ int   g_deg[N_NODES];
__device__ int   g_off[N_NODES];
__device__ int   g_rank[N_EDGES];
__device__ int   g_adj[N_EDGES];
__device__ int   g_bsum[128];
__device__ int   g_bsumoff[128];
__device__ int   g_scan_ctr;
__device__ __align__(16) __half g_Hh[(size_t)N_NODES * D];   // fp16 copy of H
__device__ __align__(16) __half g_Wh16[128 * KDIM];          // W fp16 hi
__device__ __align__(16) __half g_Wl16[128 * KDIM];          // W fp16 lo (exact to 22 bits)

// ===========================================================================
// hist + H->fp16 + W->fp16 hi/lo conversion in ONE kernel (block-range split)
// ===========================================================================
#define NB_HIST 782                        // ceil(200000/256)
#define NB_CONV 6250                       // 12.8M H elems / 8 per thread / 256
#define NB_WSPL 16                         // 32768 W elems / 8 per thread / 256

__global__ void __launch_bounds__(256) hist_conv_kernel(const int* __restrict__ src,
                                                        const float* __restrict__ H,
                                                        const float* __restrict__ W) {
    if (blockIdx.x < NB_HIST) {
        int i = blockIdx.x * blockDim.x + threadIdx.x;   // over E/8
        if (i < N_EDGES / 8) {
            int4 s0 = reinterpret_cast<const int4*>(src)[i * 2 + 0];
            int4 s1 = reinterpret_cast<const int4*>(src)[i * 2 + 1];
            int4 r0, r1;
            r0.x = atomicAdd(&g_deg[s0.x], 1);
            r0.y = atomicAdd(&g_deg[s0.y], 1);
            r0.z = atomicAdd(&g_deg[s0.z], 1);
            r0.w = atomicAdd(&g_deg[s0.w], 1);
            r1.x = atomicAdd(&g_deg[s1.x], 1);
            r1.y = atomicAdd(&g_deg[s1.y], 1);
            r1.z = atomicAdd(&g_deg[s1.z], 1);
            r1.w = atomicAdd(&g_deg[s1.w], 1);
            reinterpret_cast<int4*>(g_rank)[i * 2 + 0] = r0;
            reinterpret_cast<int4*>(g_rank)[i * 2 + 1] = r1;
        }
    } else if (blockIdx.x < NB_HIST + NB_CONV) {
        size_t j = (size_t)(blockIdx.x - NB_HIST) * blockDim.x + threadIdx.x;
        size_t base = j * 8;
        if (base < (size_t)N_NODES * D) {
            float4 a = *reinterpret_cast<const float4*>(H + base);
            float4 b = *reinterpret_cast<const float4*>(H + base + 4);
            __half2 p0 = __float22half2_rn(make_float2(a.x, a.y));
            __half2 p1 = __float22half2_rn(make_float2(a.z, a.w));
            __half2 p2 = __float22half2_rn(make_float2(b.x, b.y));
            __half2 p3 = __float22half2_rn(make_float2(b.z, b.w));
            uint4 o;
            o.x = *reinterpret_cast<uint32_t*>(&p0);
            o.y = *reinterpret_cast<uint32_t*>(&p1);
            o.z = *reinterpret_cast<uint32_t*>(&p2);
            o.w = *reinterpret_cast<uint32_t*>(&p3);
            *reinterpret_cast<uint4*>(reinterpret_cast<uint8_t*>(g_Hh) + base * 2) = o;
        }
    } else {
        // W split: 8 elems/thread
        size_t j = (size_t)(blockIdx.x - NB_HIST - NB_CONV) * blockDim.x + threadIdx.x;
        size_t base = j * 8;
        if (base < (size_t)128 * KDIM) {
#pragma unroll
            for (int u = 0; u < 8; u++) {
                float v = W[base + u];
                __half h = __float2half_rn(v);
                g_Wh16[base + u] = h;
                g_Wl16[base + u] = __float2half_rn(v - __half2float(h));
            }
        }
    }
}

// ===========================================================================
// single-launch scan: warp-shuffle block scan + last-block scans the bsums
// ===========================================================================
__global__ void __launch_bounds__(1024) scan_kernel() {
    __shared__ int wsum[32];
    __shared__ int s2[128];
    __shared__ bool is_last;

    const int tid  = threadIdx.x;
    const int lane = tid & 31;
    const int wd   = tid >> 5;
    const int i    = blockIdx.x * 1024 + tid;

    int v = (i < N_NODES) ? g_deg[i] : 0;
    int x = v;
#pragma unroll
    for (int d = 1; d < 32; d <<= 1) {
        int t = __shfl_up_sync(0xffffffffu, x, d);
        if (lane >= d) x += t;
    }
    if (lane == 31) wsum[wd] = x;
    __syncthreads();
    if (wd == 0) {
        int y = wsum[lane];
#pragma unroll
        for (int d = 1; d < 32; d <<= 1) {
            int t = __shfl_up_sync(0xffffffffu, y, d);
            if (lane >= d) y += t;
        }
        wsum[lane] = y;
    }
    __syncthreads();
    int incl = x + (wd ? wsum[wd - 1] : 0);
    if (i < N_NODES) g_off[i] = incl - v;
    if (tid == 1023) g_bsum[blockIdx.x] = incl;

    __threadfence();
    if (tid == 0) is_last = (atomicAdd(&g_scan_ctr, 1) == (int)gridDim.x - 1);
    __syncthreads();

    if (is_last) {
        int b = (tid < 128 && tid < (int)gridDim.x) ? g_bsum[tid] : 0;
        if (tid < 128) s2[tid] = b;
        __syncthreads();
        for (int ofs = 1; ofs < 128; ofs <<= 1) {
            int t = (tid < 128 && tid >= ofs) ? s2[tid - ofs] : 0;
            __syncthreads();
            if (tid < 128) s2[tid] += t;
            __syncthreads();
        }
        if (tid < 128) g_bsumoff[tid] = s2[tid] - b;
        if (tid == 0) g_scan_ctr = 0;
    }
}

// ===========================================================================
// atomic-free scatter; triggers dependent (fused) launch at entry (PDL)
// ===========================================================================
__global__ void __launch_bounds__(256) fill_adj_kernel(const int* __restrict__ src,
                                                       const int* __restrict__ dst) {
    asm volatile("griddepcontrol.launch_dependents;");
    int i = blockIdx.x * blockDim.x + threadIdx.x;
    if (i < N_EDGES / 8) {
#pragma unroll
        for (int h = 0; h < 2; h++) {
            int4 s = reinterpret_cast<const int4*>(src)[i * 2 + h];
            int4 d = reinterpret_cast<const int4*>(dst)[i * 2 + h];
            int4 r = reinterpret_cast<const int4*>(g_rank)[i * 2 + h];
            g_adj[g_off[s.x] + g_bsumoff[s.x >> 10] + r.x] = d.x;
            g_adj[g_off[s.y] + g_bsumoff[s.y >> 10] + r.y] = d.y;
            g_adj[g_off[s.z] + g_bsumoff[s.z >> 10] + r.z] = d.z;
            g_adj[g_off[s.w] + g_bsumoff[s.w >> 10] + r.w] = d.w;
        }
    }
}

// ===========================================================================
// Fused GEMM + aggregate, all-fp16 2-pass MMA (A fp16, B fp16 hi/lo):
//   out = [Hh | agg] @ (Wh + Wl)^T + b   with fp32 accumulate.
// A staging = raw byte copies from g_Hh; agg stored in smem as raw fp16.
// ===========================================================================
__device__ __forceinline__ uint32_t smem_u32(const void* p) {
    uint32_t a;
    asm("{ .reg .u64 t; cvta.to.shared.u64 t, %1; cvt.u32.u64 %0, t; }"
        : "=r"(a) : "l"(p));
    return a;
}

__device__ __forceinline__ uint32_t sw64(uint32_t b) { return b ^ ((b >> 3) & 0x30); }

__device__ __forceinline__ void ldsm_x4(uint32_t& r0, uint32_t& r1, uint32_t& r2,
                                        uint32_t& r3, uint32_t addr) {
    asm volatile("ldmatrix.sync.aligned.m8n8.x4.shared.b16 {%0,%1,%2,%3}, [%4];"
                 : "=r"(r0), "=r"(r1), "=r"(r2), "=r"(r3) : "r"(addr));
}

__device__ __forceinline__ void mma_f16(float* c, uint32_t a0, uint32_t a1,
                                        uint32_t a2, uint32_t a3,
                                        uint32_t b0, uint32_t b1) {
    asm volatile(
        "mma.sync.aligned.m16n8k16.row.col.f32.f16.f16.f32 "
        "{%0,%1,%2,%3},{%4,%5,%6,%7},{%8,%9},{%0,%1,%2,%3};"
        : "+f"(c[0]), "+f"(c[1]), "+f"(c[2]), "+f"(c[3])
        : "r"(a0), "r"(a1), "r"(a2), "r"(a3), "r"(b0), "r"(b1));
}

__device__ __forceinline__ void hmax2_acc(uint2& m, uint2 v) {
    __half2 ma = *reinterpret_cast<__half2*>(&m.x);
    __half2 mb = *reinterpret_cast<__half2*>(&m.y);
    ma = __hmax2(ma, *reinterpret_cast<const __half2*>(&v.x));
    mb = __hmax2(mb, *reinterpret_cast<const __half2*>(&v.y));
    m.x = *reinterpret_cast<uint32_t*>(&ma);
    m.y = *reinterpret_cast<uint32_t*>(&mb);
}

// dynamic smem layout (56 KB total):
//   [0,     32768): agg[4 chunks][8KB fp16]
//   [32768, 40960): sA   (H-chunk staging, fp16)
//   [40960, 49152): sBh
//   [49152, 57344): sBl
#define SM_AGG   0
#define SM_A     32768
#define SM_BH    40960
#define SM_BL    49152
#define SM_TOTAL 57344

#define NT 512

struct GemmCtx {
    uint8_t* smem;
    int mblk, tid, lane, warp_m, warp_n, lsub, lr;
    uint32_t bA, bBh, bBl, bAgg;
};

// aggregate 8 rows per warp from fp16 H copy; raw fp16 stored to smem
__device__ __forceinline__ void do_aggregate(const GemmCtx& g) {
    const int lane = g.lane;
    const int wid  = g.tid >> 5;
    const int q  = lane & 7;
    const int ch = lane >> 3;
    uint8_t* agg = g.smem + SM_AGG + ch * 8192;

    const uint8_t* Hh = reinterpret_cast<const uint8_t*>(g_Hh);
    const uint32_t lane_off = (uint32_t)lane * 8;    // bytes within 256B row

    const uint32_t NEGINF2 = 0xFC00FC00u;            // -inf fp16 x2

    for (int i = 0; i < 8; i++) {
        int mloc  = wid * 8 + i;
        int gnode = g.mblk + mloc;
        uint2 m = make_uint2(NEGINF2, NEGINF2);
        int deg = 0;
        if (gnode < N_NODES) {
            int off = g_off[gnode] + g_bsumoff[gnode >> 10];
            deg = g_deg[gnode];
            int j = 0;
            for (; j + 8 <= deg; j += 8) {
                uint2 v0 = *reinterpret_cast<const uint2*>(Hh + (size_t)g_adj[off + j + 0] * 256 + lane_off);
                uint2 v1 = *reinterpret_cast<const uint2*>(Hh + (size_t)g_adj[off + j + 1] * 256 + lane_off);
                uint2 v2 = *reinterpret_cast<const uint2*>(Hh + (size_t)g_adj[off + j + 2] * 256 + lane_off);
                uint2 v3 = *reinterpret_cast<const uint2*>(Hh + (size_t)g_adj[off + j + 3] * 256 + lane_off);
                uint2 v4 = *reinterpret_cast<const uint2*>(Hh + (size_t)g_adj[off + j + 4] * 256 + lane_off);
                uint2 v5 = *reinterpret_cast<const uint2*>(Hh + (size_t)g_adj[off + j + 5] * 256 + lane_off);
                uint2 v6 = *reinterpret_cast<const uint2*>(Hh + (size_t)g_adj[off + j + 6] * 256 + lane_off);
                uint2 v7 = *reinterpret_cast<const uint2*>(Hh + (size_t)g_adj[off + j + 7] * 256 + lane_off);
                hmax2_acc(m, v0); hmax2_acc(m, v1); hmax2_acc(m, v2); hmax2_acc(m, v3);
                hmax2_acc(m, v4); hmax2_acc(m, v5); hmax2_acc(m, v6); hmax2_acc(m, v7);
            }
            for (; j < deg; j++) {
                uint2 v = *reinterpret_cast<const uint2*>(Hh + (size_t)g_adj[off + j] * 256 + lane_off);
                hmax2_acc(m, v);
            }
        }
        if (deg == 0) m = make_uint2(0u, 0u);
        *reinterpret_cast<uint2*>(agg + sw64((uint32_t)(mloc * 64 + q * 8))) = m;
    }
}

__device__ __forceinline__ void do_chunk(const GemmCtx& g, int c, float acc[2][4][4]) {
    const int kc = c * 32;
    uint8_t* smem = g.smem;
    const int tid = g.tid;

    // ---- stage A from g_Hh (chunks 0-3 only; 4-7 read agg smem); raw copies ----
    if (c < 4) {
        int m = tid >> 2, u = tid & 3;
        int gm = g.mblk + m;
        uint4 v = make_uint4(0u, 0u, 0u, 0u);
        if (gm < N_NODES)
            v = *reinterpret_cast<const uint4*>(
                    reinterpret_cast<const uint8_t*>(g_Hh) + (size_t)gm * 256 + kc * 2 + u * 16);
        *reinterpret_cast<uint4*>(smem + SM_A + sw64((uint32_t)(m * 64 + u * 16))) = v;
    }

    // ---- stage B hi/lo from precomputed fp16 splits; raw copies ----
    {
        int n = tid >> 2, u = tid & 3;
        size_t srcoff = ((size_t)n * KDIM + kc) * 2 + u * 16;   // bytes
        uint32_t sb = sw64((uint32_t)(n * 64 + u * 16));
        *reinterpret_cast<uint4*>(smem + SM_BH + sb) =
            *reinterpret_cast<const uint4*>(reinterpret_cast<const uint8_t*>(g_Wh16) + srcoff);
        *reinterpret_cast<uint4*>(smem + SM_BL + sb) =
            *reinterpret_cast<const uint4*>(reinterpret_cast<const uint8_t*>(g_Wl16) + srcoff);
    }
    __syncthreads();

    const uint32_t aBase = (c < 4) ? g.bA : (g.bAgg + (uint32_t)(c - 4) * 8192u);

#pragma unroll
    for (int ks = 0; ks < 2; ks++) {
        const int k0 = ks * 16;
        uint32_t A[2][4];
#pragma unroll
        for (int f = 0; f < 2; f++) {
            int row = g.warp_m * 32 + f * 16 + (g.lsub & 1) * 8 + g.lr;
            int kb  = k0 + (g.lsub >> 1) * 8;
            uint32_t ofs = sw64((uint32_t)(row * 64 + kb * 2));
            ldsm_x4(A[f][0], A[f][1], A[f][2], A[f][3], aBase + ofs);
        }
#pragma unroll
        for (int np = 0; np < 2; np++) {
            int n  = g.warp_n * 32 + np * 16 + (g.lsub >> 1) * 8 + g.lr;
            int kb = k0 + (g.lsub & 1) * 8;
            uint32_t ofs = sw64((uint32_t)(n * 64 + kb * 2));
            uint32_t Bh[4], Bl[4];
            ldsm_x4(Bh[0], Bh[1], Bh[2], Bh[3], g.bBh + ofs);
            ldsm_x4(Bl[0], Bl[1], Bl[2], Bl[3], g.bBl + ofs);
#pragma unroll
            for (int f = 0; f < 2; f++) {
                mma_f16(acc[f][np * 2 + 0], A[f][0], A[f][1], A[f][2], A[f][3], Bh[0], Bh[1]);
                mma_f16(acc[f][np * 2 + 1], A[f][0], A[f][1], A[f][2], A[f][3], Bh[2], Bh[3]);
                mma_f16(acc[f][np * 2 + 0], A[f][0], A[f][1], A[f][2], A[f][3], Bl[0], Bl[1]);
                mma_f16(acc[f][np * 2 + 1], A[f][0], A[f][1], A[f][2], A[f][3], Bl[2], Bl[3]);
            }
        }
    }
    __syncthreads();
}

__global__ void __launch_bounds__(NT, 2) fused_kernel(
    const float* __restrict__ bias,
    float* __restrict__ out)
{
    extern __shared__ __align__(16) uint8_t smem[];

    GemmCtx g;
    g.smem   = smem;
    g.tid    = threadIdx.x;
    g.lane   = g.tid & 31;
    g.mblk   = blockIdx.x * 128;
    int wid  = g.tid >> 5;
    g.warp_m = wid >> 2;
    g.warp_n = wid & 3;
    g.lsub   = g.lane >> 3;
    g.lr     = g.lane & 7;
    g.bA     = smem_u32(smem + SM_A);
    g.bBh    = smem_u32(smem + SM_BH);
    g.bBl    = smem_u32(smem + SM_BL);
    g.bAgg   = smem_u32(smem + SM_AGG);

    float acc[2][4][4];
#pragma unroll
    for (int f = 0; f < 2; f++)
#pragma unroll
        for (int t = 0; t < 4; t++)
#pragma unroll
            for (int i = 0; i < 4; i++) acc[f][t][i] = 0.f;

    // ---- CSR-independent half first (overlaps fill_adj via PDL trigger) ----
    // NOTE: g_Hh/g_Wh16/g_Wl16 were produced 3 kernels upstream (transitively
    // complete); only g_adj is in flight, read after the dependency sync.
    for (int c = 0; c < 4; c++) do_chunk(g, c, acc);

    cudaGridDependencySynchronize();

    do_aggregate(g);
    // chunk 4's staging __syncthreads orders agg smem writes before ldsm reads

    for (int c = 4; c < 8; c++) do_chunk(g, c, acc);

    // ---- epilogue: add bias, store ----
    const int mbase = g.mblk + g.warp_m * 32 + (g.lane >> 2);
#pragma unroll
    for (int f = 0; f < 2; f++) {
        int row0 = mbase + f * 16;
        int row1 = row0 + 8;
#pragma unroll
        for (int t = 0; t < 4; t++) {
            int col = g.warp_n * 32 + t * 8 + (g.lane & 3) * 2;
            float2 bv = *reinterpret_cast<const float2*>(bias + col);
            if (row0 < N_NODES) {
                float2 o = make_float2(acc[f][t][0] + bv.x, acc[f][t][1] + bv.y);
                *reinterpret_cast<float2*>(out + (size_t)row0 * D + col) = o;
            }
            if (row1 < N_NODES) {
                float2 o = make_float2(acc[f][t][2] + bv.x, acc[f][t][3] + bv.y);
                *reinterpret_cast<float2*>(out + (size_t)row1 * D + col) = o;
            }
        }
    }

    // ---- self-restore g_deg to 0 for the next replay (deterministic) ----
    for (int i = g.tid; i < 128; i += NT) {
        int gn = g.mblk + i;
        if (gn < N_NODES) g_deg[gn] = 0;
    }
}

// ===========================================================================
// Launch: 3 prologue kernels + fused (PDL trigger lives in fill_adj)
// ===========================================================================
extern "C" void kernel_launch(void* const* d_in, const int* in_sizes, int n_in,
                              void* d_out, int out_size) {
    const float* H   = (const float*)d_in[0];
    const int*   src = (const int*)d_in[1];
    const int*   dst = (const int*)d_in[2];
    const float* W   = (const float*)d_in[3];
    const float* b   = (const float*)d_in[4];
    float*       out = (float*)d_out;

    cudaFuncSetAttribute(fused_kernel,
                         cudaFuncAttributeMaxDynamicSharedMemorySize, SM_TOTAL);

    const int nb_scan = (N_NODES + 1023) / 1024;   // 98
    const int nb_gemm = (N_NODES + 127) / 128;     // 782
    const int nb_e8   = (N_EDGES / 8 + 255) / 256; // 782

    hist_conv_kernel<<<NB_HIST + NB_CONV + NB_WSPL, 256>>>(src, H, W);
    scan_kernel<<<nb_scan, 1024>>>();
    fill_adj_kernel<<<nb_e8, 256>>>(src, dst);

    cudaLaunchConfig_t cfg = {};
    cfg.gridDim = dim3((unsigned)nb_gemm);
    cfg.blockDim = dim3(NT);
    cfg.dynamicSmemBytes = SM_TOTAL;
    cfg.stream = 0;
    cudaLaunchAttribute attrs[1];
    attrs[0].id = cudaLaunchAttributeProgrammaticStreamSerialization;
    attrs[0].val.programmaticStreamSerializationAllowed = 1;
    cfg.attrs = attrs;
    cfg.numAttrs = 1;
    cudaLaunchKernelEx(&cfg, fused_kernel, b, out);
}